// round 1
// baseline (speedup 1.0000x reference)
#include <cuda_runtime.h>

// ---------------- problem constants ----------------
#define BB   2
#define LL   1024
#define D4   1024
#define NSTATE 64
#define BL   2048            // BB*LL rows
#define DTR  8
#define XDBL_N 136           // DTR + 2*64

// ---------------- scratch (static device globals; no allocs) ----------------
__device__ float g_xz  [(size_t)BL * 2048];   // in_proj output: [x(1024) | z(1024)]
__device__ float g_xc  [(size_t)BL * D4];     // conv+silu output
__device__ float g_xdbl[(size_t)BL * XDBL_N]; // x @ xproj_W  -> [dlow(8) | B(64) | C(64)]
__device__ float g_dlt [(size_t)BL * D4];     // softplus(dlow@dtW + b)
__device__ float g_y   [(size_t)BL * D4];     // scan output, gated

// quaternion Hamilton tables: out group g (rr,ri,rj,rk) x input group h (r,i,j,k)
__constant__ int   c_qidx[4][4] = {{0,1,2,3},{1,0,3,2},{2,3,0,1},{3,2,1,0}};
__constant__ float c_qsgn[4][4] = {{ 1.f,-1.f,-1.f,-1.f},
                                   { 1.f, 1.f, 1.f,-1.f},
                                   { 1.f,-1.f, 1.f, 1.f},
                                   { 1.f, 1.f,-1.f, 1.f}};

// ---------------- packed f32x2 helpers ----------------
__device__ __forceinline__ unsigned long long pack2(float x, float y) {
    unsigned long long r;
    asm("mov.b64 %0, {%1,%2};" : "=l"(r) : "f"(x), "f"(y));
    return r;
}
__device__ __forceinline__ float2 unpack2(unsigned long long v) {
    float2 r;
    asm("mov.b64 {%0,%1}, %2;" : "=f"(r.x), "=f"(r.y) : "l"(v));
    return r;
}
__device__ __forceinline__ void fma2(unsigned long long& d,
                                     unsigned long long a, unsigned long long b) {
    asm("fma.rn.f32x2 %0, %1, %2, %0;" : "+l"(d) : "l"(a), "l"(b));
}

// ---------------- generic tiled GEMM (fp32, f32x2 accumulate) ----------------
// MODE 0: A = concat(q_r,q_i,q_j,q_k) [2048,512], B = quaternion in_W (512x2048 eff), C=g_xz
// MODE 1: A plain [M,K], B plain [K,N] (xproj), C=g_xdbl
// MODE 2: A plain (g_y), B = quaternion out_W (1024x512 eff), C=d_out
template<int MODE, int BM, int BN, int BK, int TM, int TN>
__global__ void __launch_bounds__(256) gemm_kernel(
    const float* __restrict__ A,
    const float* __restrict__ Q0, const float* __restrict__ Q1,
    const float* __restrict__ Q2, const float* __restrict__ Q3,
    const float* __restrict__ W0, const float* __restrict__ W1,
    const float* __restrict__ W2, const float* __restrict__ W3,
    const float* __restrict__ Bp,
    float* __restrict__ Cout,
    int M, int N, int K)
{
    constexpr int NT  = (BM/TM) * (BN/TN);   // 256 for both configs
    constexpr int TNV = TN / 4;              // float4 column chunks per thread
    constexpr int CSTRIDE = 64;              // chunk-to-chunk column stride
    constexpr int WCOL = (MODE == 0) ? 512 : 128;
    constexpr int NSH  = (MODE == 0) ? 9 : 7;
    constexpr int KSH  = (MODE == 0) ? 7 : 8;

    __shared__ float As[BK][BM + 4];
    __shared__ float Bs[BK][BN + 4];

    const int tid = threadIdx.x;
    const int bn0 = blockIdx.x * BN;
    const int bm0 = blockIdx.y * BM;
    const int tx  = tid % (BN / TN);
    const int ty  = tid / (BN / TN);

    unsigned long long acc[TM][TNV][2];
    #pragma unroll
    for (int i = 0; i < TM; i++)
        #pragma unroll
        for (int c = 0; c < TNV; c++) { acc[i][c][0] = 0ull; acc[i][c][1] = 0ull; }

    for (int kb = 0; kb < K; kb += BK) {
        // ---- load A tile (store transposed: As[k][m]) ----
        #pragma unroll
        for (int i = tid; i < BM * BK; i += NT) {
            int r = i / BK, c = i % BK;
            int m = bm0 + r, k = kb + c;
            float v;
            if (MODE == 0) {
                const float* q = (k < 128) ? Q0 : (k < 256) ? Q1 : (k < 384) ? Q2 : Q3;
                v = q[(size_t)m * 128 + (k & 127)];
            } else {
                v = A[(size_t)m * K + k];
            }
            As[c][r] = v;
        }
        // ---- load B tile (gather quaternion-structured weights on the fly) ----
        #pragma unroll
        for (int i = tid; i < BK * BN; i += NT) {
            int r = i / BN, c = i % BN;
            int k = kb + r, n = bn0 + c;
            float v;
            if (MODE == 1) {
                v = (n < N) ? Bp[(size_t)k * N + n] : 0.f;
            } else {
                int g = n >> NSH, h = k >> KSH;
                int wi = c_qidx[g][h];
                const float* Wt = (wi == 0) ? W0 : (wi == 1) ? W1 : (wi == 2) ? W2 : W3;
                v = c_qsgn[g][h] * Wt[(size_t)(k & ((1 << KSH) - 1)) * WCOL
                                      + (n & ((1 << NSH) - 1))];
            }
            Bs[r][c] = v;
        }
        __syncthreads();

        #pragma unroll
        for (int k = 0; k < BK; k++) {
            float4 av[TM / 4];
            #pragma unroll
            for (int r = 0; r < TM / 4; r++)
                av[r] = *(const float4*)&As[k][ty * TM + 4 * r];
            unsigned long long b01[TNV], b23[TNV];
            #pragma unroll
            for (int c = 0; c < TNV; c++) {
                float4 bv = *(const float4*)&Bs[k][c * CSTRIDE + tx * 4];
                b01[c] = pack2(bv.x, bv.y);
                b23[c] = pack2(bv.z, bv.w);
            }
            const float* af = (const float*)av;
            #pragma unroll
            for (int i = 0; i < TM; i++) {
                unsigned long long ap = pack2(af[i], af[i]);
                #pragma unroll
                for (int c = 0; c < TNV; c++) {
                    fma2(acc[i][c][0], ap, b01[c]);
                    fma2(acc[i][c][1], ap, b23[c]);
                }
            }
        }
        __syncthreads();
    }

    // ---- epilogue ----
    #pragma unroll
    for (int i = 0; i < TM; i++) {
        int m = bm0 + ty * TM + i;
        #pragma unroll
        for (int c = 0; c < TNV; c++) {
            int n = bn0 + c * CSTRIDE + tx * 4;
            float2 v0 = unpack2(acc[i][c][0]);
            float2 v1 = unpack2(acc[i][c][1]);
            if (n + 3 < N) {
                float4 o; o.x = v0.x; o.y = v0.y; o.z = v1.x; o.w = v1.y;
                *(float4*)&Cout[(size_t)m * N + n] = o;
            } else {
                if (n     < N) Cout[(size_t)m * N + n    ] = v0.x;
                if (n + 1 < N) Cout[(size_t)m * N + n + 1] = v0.y;
                if (n + 2 < N) Cout[(size_t)m * N + n + 2] = v1.x;
            }
        }
    }
}

// ---------------- causal depthwise conv1d (k=4) + bias + SiLU ----------------
__global__ void conv_silu_kernel(const float* __restrict__ cw,
                                 const float* __restrict__ cb)
{
    int idx = blockIdx.x * blockDim.x + threadIdx.x;
    if (idx >= BL * D4) return;
    int d  = idx & 1023;
    int l  = (idx >> 10) & 1023;
    int bl = idx >> 10;
    float w0 = cw[d * 4], w1 = cw[d * 4 + 1], w2 = cw[d * 4 + 2], w3 = cw[d * 4 + 3];
    const float* xcol = g_xz + d;          // x = first 1024 cols of g_xz
    float acc = cb[d];
    if (l >= 3) acc = fmaf(xcol[(size_t)(bl - 3) * 2048], w0, acc);
    if (l >= 2) acc = fmaf(xcol[(size_t)(bl - 2) * 2048], w1, acc);
    if (l >= 1) acc = fmaf(xcol[(size_t)(bl - 1) * 2048], w2, acc);
    acc = fmaf(xcol[(size_t)bl * 2048], w3, acc);
    float s = 1.f / (1.f + __expf(-acc));
    g_xc[idx] = acc * s;
}

// ---------------- delta = softplus(dlow @ dtproj_W + b) ----------------
__global__ void delta_kernel(const float* __restrict__ dtW,
                             const float* __restrict__ dtb)
{
    int idx = blockIdx.x * blockDim.x + threadIdx.x;
    if (idx >= BL * D4) return;
    int n = idx & 1023;
    int m = idx >> 10;
    const float* xr = g_xdbl + (size_t)m * XDBL_N;
    float acc = dtb[n];
    #pragma unroll
    for (int k = 0; k < DTR; k++)
        acc = fmaf(xr[k], dtW[k * 1024 + n], acc);
    g_dlt[idx] = (acc > 20.f) ? acc : log1pf(__expf(acc));
}

// ---------------- selective scan: 1 warp per (b,d), 2 states/lane ----------------
__global__ void scan_kernel(const float* __restrict__ A_log,
                            const float* __restrict__ D_skip)
{
    int gw   = (blockIdx.x * blockDim.x + threadIdx.x) >> 5;
    int lane = threadIdx.x & 31;
    if (gw >= BB * D4) return;
    int b = gw >> 10;
    int d = gw & 1023;
    int n0 = lane << 1;

    float a0 = -__expf(A_log[d * 64 + n0]);
    float a1 = -__expf(A_log[d * 64 + n0 + 1]);
    float Dd = D_skip[d];
    float h0 = 0.f, h1 = 0.f;

    size_t rbase = (size_t)b * 1024;
    for (int t = 0; t < 1024; t++) {
        size_t row = rbase + t;
        float dt = g_dlt[row * 1024 + d];
        float xv = g_xc [row * 1024 + d];
        const float* xd = g_xdbl + row * XDBL_N;
        float2 Bv = *(const float2*)(xd + DTR + n0);        // B at cols [8,72)
        float2 Cv = *(const float2*)(xd + DTR + 64 + n0);   // C at cols [72,136)

        float dx = dt * xv;
        h0 = fmaf(__expf(dt * a0), h0, dx * Bv.x);
        h1 = fmaf(__expf(dt * a1), h1, dx * Bv.y);
        float p = fmaf(h0, Cv.x, h1 * Cv.y);

        p += __shfl_xor_sync(0xffffffffu, p, 16);
        p += __shfl_xor_sync(0xffffffffu, p, 8);
        p += __shfl_xor_sync(0xffffffffu, p, 4);
        p += __shfl_xor_sync(0xffffffffu, p, 2);
        p += __shfl_xor_sync(0xffffffffu, p, 1);

        if (lane == 0) {
            float zv = g_xz[row * 2048 + 1024 + d];         // z = cols [1024,2048)
            float s  = 1.f / (1.f + __expf(-zv));
            g_y[row * 1024 + d] = (p + xv * Dd) * (zv * s);
        }
    }
}

// ---------------- launcher ----------------
extern "C" void kernel_launch(void* const* d_in, const int* in_sizes, int n_in,
                              void* d_out, int out_size)
{
    const float* q_r   = (const float*)d_in[0];
    const float* q_i   = (const float*)d_in[1];
    const float* q_j   = (const float*)d_in[2];
    const float* q_k   = (const float*)d_in[3];
    const float* inWr  = (const float*)d_in[4];
    const float* inWi  = (const float*)d_in[5];
    const float* inWj  = (const float*)d_in[6];
    const float* inWk  = (const float*)d_in[7];
    const float* convw = (const float*)d_in[8];
    const float* convb = (const float*)d_in[9];
    const float* xprojW= (const float*)d_in[10];
    const float* dtW   = (const float*)d_in[11];
    const float* dtb   = (const float*)d_in[12];
    const float* A_log = (const float*)d_in[13];
    const float* Dskip = (const float*)d_in[14];
    const float* outWr = (const float*)d_in[15];
    const float* outWi = (const float*)d_in[16];
    const float* outWj = (const float*)d_in[17];
    const float* outWk = (const float*)d_in[18];

    float *xz, *xc, *xdbl, *yb;
    cudaGetSymbolAddress((void**)&xz,   g_xz);
    cudaGetSymbolAddress((void**)&xc,   g_xc);
    cudaGetSymbolAddress((void**)&xdbl, g_xdbl);
    cudaGetSymbolAddress((void**)&yb,   g_y);

    // 1) quaternion in_proj: [2048,512] x [512,2048] -> g_xz
    gemm_kernel<0,128,128,16,8,8><<<dim3(16, 16), 256>>>(
        nullptr, q_r, q_i, q_j, q_k,
        inWr, inWi, inWj, inWk, nullptr, xz, BL, 2048, 512);

    // 2) depthwise conv + bias + SiLU -> g_xc
    conv_silu_kernel<<<(BL * D4) / 256, 256>>>(convw, convb);

    // 3) x_proj: [2048,1024] x [1024,136] -> g_xdbl
    gemm_kernel<1,64,64,16,4,4><<<dim3(3, 32), 256>>>(
        xc, nullptr, nullptr, nullptr, nullptr,
        nullptr, nullptr, nullptr, nullptr, xprojW, xdbl, BL, XDBL_N, 1024);

    // 4) delta = softplus(dlow @ dtW + b) -> g_dlt
    delta_kernel<<<(BL * D4) / 256, 256>>>(dtW, dtb);

    // 5) selective scan + skip + z-gate -> g_y
    scan_kernel<<<(BB * D4) / 8, 256>>>(A_log, Dskip);

    // 6) quaternion out_proj: [2048,1024] x [1024,512] -> d_out
    gemm_kernel<2,64,64,16,4,4><<<dim3(8, 32), 256>>>(
        yb, nullptr, nullptr, nullptr, nullptr,
        outWr, outWi, outWj, outWk, nullptr, (float*)d_out, BL, 512, 1024);
}

// round 2
// speedup vs baseline: 2.1081x; 2.1081x over previous
#include <cuda_runtime.h>

// ---------------- problem constants ----------------
#define BB   2
#define LL   1024
#define D4   1024
#define BL   2048            // BB*LL rows
#define DTR  8
#define XDBL_N 136           // DTR + 2*64

// ---------------- scratch (static device globals; no allocs) ----------------
__device__ float g_xz  [(size_t)BL * 2048];   // in_proj output: [x(1024) | z(1024)]
__device__ float g_xc  [(size_t)BL * D4];     // conv+silu output
__device__ float g_xdbl[(size_t)BL * XDBL_N]; // x @ xproj_W  -> [dlow(8) | B(64) | C(64)]
__device__ float g_dlt [(size_t)BL * D4];     // softplus(dlow@dtW + b)
__device__ float g_y   [(size_t)BL * D4];     // scan output, gated
__device__ float g_win [(size_t)512 * 2048];  // expanded quaternion in_proj weight
__device__ float g_wout[(size_t)1024 * 512];  // expanded quaternion out_proj weight

// quaternion Hamilton tables: out group g x input group h
__constant__ int   c_qidx[4][4] = {{0,1,2,3},{1,0,3,2},{2,3,0,1},{3,2,1,0}};
__constant__ float c_qsgn[4][4] = {{ 1.f,-1.f,-1.f,-1.f},
                                   { 1.f, 1.f, 1.f,-1.f},
                                   { 1.f,-1.f, 1.f, 1.f},
                                   { 1.f, 1.f,-1.f, 1.f}};

// ---------------- packed f32x2 helpers ----------------
__device__ __forceinline__ unsigned long long pack2(float x, float y) {
    unsigned long long r;
    asm("mov.b64 %0, {%1,%2};" : "=l"(r) : "f"(x), "f"(y));
    return r;
}
__device__ __forceinline__ unsigned long long dup2(float x) {
    unsigned long long r;
    asm("mov.b64 %0, {%1,%1};" : "=l"(r) : "f"(x));
    return r;
}
__device__ __forceinline__ float2 unpack2(unsigned long long v) {
    float2 r;
    asm("mov.b64 {%0,%1}, %2;" : "=f"(r.x), "=f"(r.y) : "l"(v));
    return r;
}
__device__ __forceinline__ void fma2(unsigned long long& d,
                                     unsigned long long a, unsigned long long b) {
    asm("fma.rn.f32x2 %0, %1, %2, %0;" : "+l"(d) : "l"(a), "l"(b));
}

// ---------------- weight expansion prologue ----------------
__global__ void expand_kernel(
    const float* __restrict__ iWr, const float* __restrict__ iWi,
    const float* __restrict__ iWj, const float* __restrict__ iWk,
    const float* __restrict__ oWr, const float* __restrict__ oWi,
    const float* __restrict__ oWj, const float* __restrict__ oWk)
{
    int idx = blockIdx.x * blockDim.x + threadIdx.x;
    const int NIN = 512 * 2048;
    if (idx < NIN) {
        int k = idx >> 11, n = idx & 2047;
        int g = n >> 9, h = k >> 7;
        int wi = c_qidx[g][h];
        const float* W = (wi == 0) ? iWr : (wi == 1) ? iWi : (wi == 2) ? iWj : iWk;
        g_win[idx] = c_qsgn[g][h] * W[(size_t)(k & 127) * 512 + (n & 511)];
    } else {
        int j = idx - NIN;
        if (j >= 1024 * 512) return;
        int k = j >> 9, n = j & 511;
        int g = n >> 7, h = k >> 8;
        int wi = c_qidx[g][h];
        const float* W = (wi == 0) ? oWr : (wi == 1) ? oWi : (wi == 2) ? oWj : oWk;
        g_wout[j] = c_qsgn[g][h] * W[(size_t)(k & 255) * 128 + (n & 127)];
    }
}

// ---------------- tiled GEMM, register-prefetch pipeline, f32x2 ----------------
// QA: A is concat(q_r,q_i,q_j,q_k) along K (each [M,128]); MASKN: mask columns >= N
template<bool QA, bool MASKN, int BM, int BN, int BK, int TM, int TN>
__global__ void __launch_bounds__(256, 2) gemm_kernel(
    const float* __restrict__ A,
    const float* __restrict__ Q0, const float* __restrict__ Q1,
    const float* __restrict__ Q2, const float* __restrict__ Q3,
    const float* __restrict__ Bm,
    float* __restrict__ Cout,
    int M, int N, int K)
{
    constexpr int NT  = (BM / TM) * (BN / TN);   // must be 256
    static_assert(NT == 256, "thread count");
    constexpr int TNV = TN / 4;
    constexpr int CSTRIDE = BN / TNV;
    constexpr int AF = BM * BK / (NT * 4);       // float4 A loads per thread
    constexpr int BF = BK * BN / (NT * 4);

    __shared__ float As[BK][BM + 4];
    __shared__ float Bs[BK][BN + 4];

    const int tid = threadIdx.x;
    const int bn0 = blockIdx.x * BN;
    const int bm0 = blockIdx.y * BM;
    const int tx  = tid % (BN / TN);
    const int ty  = tid / (BN / TN);

    unsigned long long acc[TM][TNV][2];
    #pragma unroll
    for (int i = 0; i < TM; i++)
        #pragma unroll
        for (int c = 0; c < TNV; c++) { acc[i][c][0] = 0ull; acc[i][c][1] = 0ull; }

    float4 ra[AF], rb[BF];

    auto loadA = [&](int kb) {
        #pragma unroll
        for (int j = 0; j < AF; j++) {
            int i = tid + j * NT;
            int r = i / (BK / 4), cq = i % (BK / 4);
            if (QA) {
                const float* q = ((kb >> 7) == 0) ? Q0 : ((kb >> 7) == 1) ? Q1
                               : ((kb >> 7) == 2) ? Q2 : Q3;
                ra[j] = *(const float4*)(q + (size_t)(bm0 + r) * 128 + (kb & 127) + cq * 4);
            } else {
                ra[j] = *(const float4*)(A + (size_t)(bm0 + r) * K + kb + cq * 4);
            }
        }
    };
    auto loadB = [&](int kb) {
        #pragma unroll
        for (int j = 0; j < BF; j++) {
            int i = tid + j * NT;
            int r = i / (BN / 4), c = i % (BN / 4);
            int n = bn0 + c * 4;
            if (MASKN) {
                float4 v; const float* p = Bm + (size_t)(kb + r) * N + n;
                v.x = (n     < N) ? p[0] : 0.f;
                v.y = (n + 1 < N) ? p[1] : 0.f;
                v.z = (n + 2 < N) ? p[2] : 0.f;
                v.w = (n + 3 < N) ? p[3] : 0.f;
                rb[j] = v;
            } else {
                rb[j] = *(const float4*)(Bm + (size_t)(kb + r) * N + n);
            }
        }
    };

    loadA(0); loadB(0);

    for (int kb = 0; kb < K; kb += BK) {
        // commit prefetched tile to smem
        #pragma unroll
        for (int j = 0; j < AF; j++) {
            int i = tid + j * NT;
            int r = i / (BK / 4), cq = i % (BK / 4);
            As[cq * 4 + 0][r] = ra[j].x;
            As[cq * 4 + 1][r] = ra[j].y;
            As[cq * 4 + 2][r] = ra[j].z;
            As[cq * 4 + 3][r] = ra[j].w;
        }
        #pragma unroll
        for (int j = 0; j < BF; j++) {
            int i = tid + j * NT;
            int r = i / (BN / 4), c = i % (BN / 4);
            *(float4*)&Bs[r][c * 4] = rb[j];
        }
        __syncthreads();

        if (kb + BK < K) { loadA(kb + BK); loadB(kb + BK); }

        #pragma unroll
        for (int k = 0; k < BK; k++) {
            float4 av[TM / 4];
            #pragma unroll
            for (int r = 0; r < TM / 4; r++)
                av[r] = *(const float4*)&As[k][ty * TM + 4 * r];
            unsigned long long b01[TNV], b23[TNV];
            #pragma unroll
            for (int c = 0; c < TNV; c++) {
                float4 bv = *(const float4*)&Bs[k][c * CSTRIDE + tx * 4];
                b01[c] = pack2(bv.x, bv.y);
                b23[c] = pack2(bv.z, bv.w);
            }
            const float* af = (const float*)av;
            #pragma unroll
            for (int i = 0; i < TM; i++) {
                unsigned long long ap = dup2(af[i]);
                #pragma unroll
                for (int c = 0; c < TNV; c++) {
                    fma2(acc[i][c][0], ap, b01[c]);
                    fma2(acc[i][c][1], ap, b23[c]);
                }
            }
        }
        __syncthreads();
    }

    #pragma unroll
    for (int i = 0; i < TM; i++) {
        int m = bm0 + ty * TM + i;
        #pragma unroll
        for (int c = 0; c < TNV; c++) {
            int n = bn0 + c * CSTRIDE + tx * 4;
            float2 v0 = unpack2(acc[i][c][0]);
            float2 v1 = unpack2(acc[i][c][1]);
            if (!MASKN || n + 3 < N) {
                float4 o; o.x = v0.x; o.y = v0.y; o.z = v1.x; o.w = v1.y;
                *(float4*)&Cout[(size_t)m * N + n] = o;
            } else {
                if (n     < N) Cout[(size_t)m * N + n    ] = v0.x;
                if (n + 1 < N) Cout[(size_t)m * N + n + 1] = v0.y;
                if (n + 2 < N) Cout[(size_t)m * N + n + 2] = v1.x;
            }
        }
    }
}

// ---------------- causal depthwise conv1d (k=4) + bias + SiLU ----------------
__global__ void conv_silu_kernel(const float* __restrict__ cw,
                                 const float* __restrict__ cb)
{
    int idx = blockIdx.x * blockDim.x + threadIdx.x;
    if (idx >= BL * D4) return;
    int d  = idx & 1023;
    int l  = (idx >> 10) & 1023;
    int bl = idx >> 10;
    float w0 = cw[d * 4], w1 = cw[d * 4 + 1], w2 = cw[d * 4 + 2], w3 = cw[d * 4 + 3];
    const float* xcol = g_xz + d;          // x = first 1024 cols of g_xz
    float acc = cb[d];
    if (l >= 3) acc = fmaf(xcol[(size_t)(bl - 3) * 2048], w0, acc);
    if (l >= 2) acc = fmaf(xcol[(size_t)(bl - 2) * 2048], w1, acc);
    if (l >= 1) acc = fmaf(xcol[(size_t)(bl - 1) * 2048], w2, acc);
    acc = fmaf(xcol[(size_t)bl * 2048], w3, acc);
    float s = 1.f / (1.f + __expf(-acc));
    g_xc[idx] = acc * s;
}

// ---------------- delta = softplus(dlow @ dtproj_W + b) ----------------
__global__ void delta_kernel(const float* __restrict__ dtW,
                             const float* __restrict__ dtb)
{
    int idx = blockIdx.x * blockDim.x + threadIdx.x;
    if (idx >= BL * D4) return;
    int n = idx & 1023;
    int m = idx >> 10;
    const float* xr = g_xdbl + (size_t)m * XDBL_N;
    float acc = dtb[n];
    #pragma unroll
    for (int k = 0; k < DTR; k++)
        acc = fmaf(xr[k], dtW[k * 1024 + n], acc);
    g_dlt[idx] = (acc > 20.f) ? acc : log1pf(__expf(acc));
}

// ---------------- selective scan v2: smem-staged chunks ----------------
// block: 128 threads = 4 warps = 4 channels d; grid (256, BB); chunk of 64 timesteps
#define TC 64
__global__ void __launch_bounds__(128) scan_kernel(
    const float* __restrict__ A_log,
    const float* __restrict__ D_skip)
{
    __shared__ float Bsh[TC][64];
    __shared__ float Csh[TC][64];
    __shared__ float dts[4][TC], xcs[4][TC], zsh[4][TC], ysh[4][TC];

    const int b    = blockIdx.y;
    const int d0   = blockIdx.x * 4;
    const int tid  = threadIdx.x;
    const int wi   = tid >> 5;
    const int lane = tid & 31;
    const int d    = d0 + wi;
    const int n0   = lane << 1;

    const float a0 = -__expf(A_log[d * 64 + n0]);
    const float a1 = -__expf(A_log[d * 64 + n0 + 1]);
    const float Dd = D_skip[d];
    float h0 = 0.f, h1 = 0.f;

    const size_t rbase = (size_t)b * 1024;

    for (int c = 0; c < 1024 / TC; c++) {
        const int t0 = c * TC;
        // cooperative loads: B/C tiles (64 t x 64 n each)
        #pragma unroll 4
        for (int i = tid; i < TC * 32; i += 128) {
            int t = i >> 5, q = i & 31;
            const float* xd = g_xdbl + (rbase + t0 + t) * XDBL_N + DTR;
            float2 bv = *(const float2*)(xd + 2 * q);
            float2 cv = *(const float2*)(xd + 64 + 2 * q);
            *(float2*)&Bsh[t][2 * q] = bv;
            *(float2*)&Csh[t][2 * q] = cv;
        }
        // dt / xc / z tiles (4 d x 64 t)
        #pragma unroll 2
        for (int i = tid; i < 4 * TC; i += 128) {
            int t = i >> 2, di = i & 3;
            size_t row = rbase + t0 + t;
            dts[di][t] = g_dlt[row * 1024 + d0 + di];
            xcs[di][t] = g_xc [row * 1024 + d0 + di];
            zsh[di][t] = g_xz [row * 2048 + 1024 + d0 + di];
        }
        __syncthreads();

        #pragma unroll 4
        for (int t = 0; t < TC; t++) {
            float dt = dts[wi][t];
            float xv = xcs[wi][t];
            float2 Bv = *(const float2*)&Bsh[t][n0];
            float2 Cv = *(const float2*)&Csh[t][n0];
            float dx = dt * xv;
            h0 = fmaf(__expf(dt * a0), h0, dx * Bv.x);
            h1 = fmaf(__expf(dt * a1), h1, dx * Bv.y);
            float p = fmaf(h0, Cv.x, h1 * Cv.y);
            p += __shfl_xor_sync(0xffffffffu, p, 16);
            p += __shfl_xor_sync(0xffffffffu, p, 8);
            p += __shfl_xor_sync(0xffffffffu, p, 4);
            p += __shfl_xor_sync(0xffffffffu, p, 2);
            p += __shfl_xor_sync(0xffffffffu, p, 1);
            if (lane == 0) {
                float zv = zsh[wi][t];
                float s  = zv / (1.f + __expf(-zv));
                ysh[wi][t] = (p + xv * Dd) * s;
            }
        }
        __syncthreads();

        #pragma unroll 2
        for (int i = tid; i < 4 * TC; i += 128) {
            int t = i >> 2, di = i & 3;
            g_y[(rbase + t0 + t) * 1024 + d0 + di] = ysh[di][t];
        }
        __syncthreads();
    }
}

// ---------------- launcher ----------------
extern "C" void kernel_launch(void* const* d_in, const int* in_sizes, int n_in,
                              void* d_out, int out_size)
{
    const float* q_r   = (const float*)d_in[0];
    const float* q_i   = (const float*)d_in[1];
    const float* q_j   = (const float*)d_in[2];
    const float* q_k   = (const float*)d_in[3];
    const float* inWr  = (const float*)d_in[4];
    const float* inWi  = (const float*)d_in[5];
    const float* inWj  = (const float*)d_in[6];
    const float* inWk  = (const float*)d_in[7];
    const float* convw = (const float*)d_in[8];
    const float* convb = (const float*)d_in[9];
    const float* xprojW= (const float*)d_in[10];
    const float* dtW   = (const float*)d_in[11];
    const float* dtb   = (const float*)d_in[12];
    const float* A_log = (const float*)d_in[13];
    const float* Dskip = (const float*)d_in[14];
    const float* outWr = (const float*)d_in[15];
    const float* outWi = (const float*)d_in[16];
    const float* outWj = (const float*)d_in[17];
    const float* outWk = (const float*)d_in[18];

    float *xz, *xc, *xdbl, *yb, *win, *wout;
    cudaGetSymbolAddress((void**)&xz,   g_xz);
    cudaGetSymbolAddress((void**)&xc,   g_xc);
    cudaGetSymbolAddress((void**)&xdbl, g_xdbl);
    cudaGetSymbolAddress((void**)&yb,   g_y);
    cudaGetSymbolAddress((void**)&win,  g_win);
    cudaGetSymbolAddress((void**)&wout, g_wout);

    // 0) expand quaternion weights into plain matrices
    {
        int total = 512 * 2048 + 1024 * 512;
        expand_kernel<<<(total + 255) / 256, 256>>>(
            inWr, inWi, inWj, inWk, outWr, outWi, outWj, outWk);
    }

    // 1) quaternion in_proj: [2048,512] x [512,2048] -> g_xz
    gemm_kernel<true, false, 128, 128, 16, 8, 8><<<dim3(16, 16), 256>>>(
        nullptr, q_r, q_i, q_j, q_k, win, xz, BL, 2048, 512);

    // 2) depthwise conv + bias + SiLU -> g_xc
    conv_silu_kernel<<<(BL * D4) / 256, 256>>>(convw, convb);

    // 3) x_proj: [2048,1024] x [1024,136] -> g_xdbl
    gemm_kernel<false, true, 64, 64, 16, 4, 4><<<dim3(3, 32), 256>>>(
        xc, nullptr, nullptr, nullptr, nullptr, xprojW, xdbl, BL, XDBL_N, 1024);

    // 4) delta = softplus(dlow @ dtW + b) -> g_dlt
    delta_kernel<<<(BL * D4) / 256, 256>>>(dtW, dtb);

    // 5) selective scan + skip + z-gate -> g_y (smem-staged)
    scan_kernel<<<dim3(256, BB), 128>>>(A_log, Dskip);

    // 6) quaternion out_proj: [2048,1024] x [1024,512] -> d_out
    gemm_kernel<false, false, 128, 64, 16, 8, 4><<<dim3(8, 16), 256>>>(
        yb, nullptr, nullptr, nullptr, nullptr, wout, (float*)d_out, BL, 512, 1024);
}

// round 4
// speedup vs baseline: 2.1529x; 1.0213x over previous
#include <cuda_runtime.h>

typedef unsigned long long ull;

// ---------------- problem constants ----------------
#define BB   2
#define LL   1024
#define D4   1024
#define BL   2048            // BB*LL rows
#define DTR  8
#define XDBL_N 136           // DTR + 2*64
#define XSPLIT 8             // split-K factor for xproj

// ---------------- scratch (static device globals; no allocs) ----------------
__device__ float g_xz  [(size_t)BL * 2048];   // in_proj output: [x(1024) | z(1024)]
__device__ float g_xc  [(size_t)BL * D4];     // conv+silu output
__device__ float g_xdbl[(size_t)BL * XDBL_N]; // x @ xproj_W  -> [dlow(8) | B(64) | C(64)]
__device__ float g_xp  [(size_t)XSPLIT * BL * XDBL_N]; // split-K partials
__device__ float g_dlt [(size_t)BL * D4];     // softplus(dlow@dtW + b)
__device__ float g_y   [(size_t)BL * D4];     // scan output, gated
__device__ float g_win [(size_t)512 * 2048];  // expanded quaternion in_proj weight
__device__ float g_wout[(size_t)1024 * 512];  // expanded quaternion out_proj weight

// quaternion Hamilton tables: out group g x input group h
__constant__ int   c_qidx[4][4] = {{0,1,2,3},{1,0,3,2},{2,3,0,1},{3,2,1,0}};
__constant__ float c_qsgn[4][4] = {{ 1.f,-1.f,-1.f,-1.f},
                                   { 1.f, 1.f, 1.f,-1.f},
                                   { 1.f,-1.f, 1.f, 1.f},
                                   { 1.f, 1.f,-1.f, 1.f}};

// ---------------- packed f32x2 helpers ----------------
__device__ __forceinline__ ull pack2(float x, float y) {
    ull r; asm("mov.b64 %0, {%1,%2};" : "=l"(r) : "f"(x), "f"(y)); return r;
}
__device__ __forceinline__ ull dup2(float x) {
    ull r; asm("mov.b64 %0, {%1,%1};" : "=l"(r) : "f"(x)); return r;
}
__device__ __forceinline__ float2 unpack2(ull v) {
    float2 r; asm("mov.b64 {%0,%1}, %2;" : "=f"(r.x), "=f"(r.y) : "l"(v)); return r;
}
__device__ __forceinline__ void fma2(ull& d, ull a, ull b) {
    asm("fma.rn.f32x2 %0, %1, %2, %0;" : "+l"(d) : "l"(a), "l"(b));
}

// ---------------- weight expansion prologue ----------------
__global__ void expand_kernel(
    const float* __restrict__ iWr, const float* __restrict__ iWi,
    const float* __restrict__ iWj, const float* __restrict__ iWk,
    const float* __restrict__ oWr, const float* __restrict__ oWi,
    const float* __restrict__ oWj, const float* __restrict__ oWk)
{
    int idx = blockIdx.x * blockDim.x + threadIdx.x;
    const int NIN = 512 * 2048;
    if (idx < NIN) {
        int k = idx >> 11, n = idx & 2047;
        int g = n >> 9, h = k >> 7;
        int wi = c_qidx[g][h];
        const float* W = (wi == 0) ? iWr : (wi == 1) ? iWi : (wi == 2) ? iWj : iWk;
        g_win[idx] = c_qsgn[g][h] * W[(size_t)(k & 127) * 512 + (n & 511)];
    } else {
        int j = idx - NIN;
        if (j >= 1024 * 512) return;
        int k = j >> 9, n = j & 511;
        int g = n >> 7, h = k >> 8;
        int wi = c_qidx[g][h];
        const float* W = (wi == 0) ? oWr : (wi == 1) ? oWi : (wi == 2) ? oWj : oWk;
        g_wout[j] = c_qsgn[g][h] * W[(size_t)(k & 255) * 128 + (n & 127)];
    }
}

// ---------------- tiled GEMM: BK=32, M-pair f32x2, frag double-buffer ----------------
// QA: A is concat(q_r..q_k) along K; MASKN: guard columns >= N; Kc: K-chunk per z-slice
template<bool QA, bool MASKN, int BM, int BN, int BK, int TM, int TN, int NB>
__global__ void __launch_bounds__(256, NB) gemm_kernel(
    const float* __restrict__ A,
    const float* __restrict__ Q0, const float* __restrict__ Q1,
    const float* __restrict__ Q2, const float* __restrict__ Q3,
    const float* __restrict__ Bm,
    float* __restrict__ Cout,
    int M, int N, int K, int Kc)
{
    constexpr int NT  = 256;
    static_assert((BM / TM) * (BN / TN) == NT, "thread count");
    constexpr int TMH = TM / 2;                  // m-pairs
    constexpr int TNV = TN / 4;                  // float4 column chunks
    constexpr int CST = BN / TNV;                // chunk stride
    constexpr int AF  = BM * BK / (NT * 4);
    constexpr int BF  = BK * BN / (NT * 4);

    __shared__ float As[BK][BM + 4];
    __shared__ float Bs[BK][BN + 4];

    const int tid = threadIdx.x;
    const int bn0 = blockIdx.x * BN;
    const int bm0 = blockIdx.y * BM;
    const int kb0 = blockIdx.z * Kc;
    const int tx  = tid % (BN / TN);
    const int ty  = tid / (BN / TN);

    ull acc[TMH][TNV][4];
    #pragma unroll
    for (int i = 0; i < TMH; i++)
        #pragma unroll
        for (int c = 0; c < TNV; c++)
            #pragma unroll
            for (int j = 0; j < 4; j++) acc[i][c][j] = 0ull;

    float4 ra[AF], rb[BF];

    auto loadA = [&](int kb) {
        #pragma unroll
        for (int j = 0; j < AF; j++) {
            int i = tid + j * NT;
            int r = i / (BK / 4), cq = i % (BK / 4);
            if (QA) {
                const float* q = ((kb >> 7) == 0) ? Q0 : ((kb >> 7) == 1) ? Q1
                               : ((kb >> 7) == 2) ? Q2 : Q3;
                ra[j] = *(const float4*)(q + (size_t)(bm0 + r) * 128 + (kb & 127) + cq * 4);
            } else {
                ra[j] = *(const float4*)(A + (size_t)(bm0 + r) * K + kb + cq * 4);
            }
        }
    };
    auto loadB = [&](int kb) {
        #pragma unroll
        for (int j = 0; j < BF; j++) {
            int i = tid + j * NT;
            int r = i / (BN / 4), c = i % (BN / 4);
            int n = bn0 + c * 4;
            if (MASKN && n + 3 >= N) rb[j] = make_float4(0.f, 0.f, 0.f, 0.f);
            else rb[j] = *(const float4*)(Bm + (size_t)(kb + r) * N + n);
        }
    };

    loadA(kb0); loadB(kb0);

    for (int kb = kb0; kb < kb0 + Kc; kb += BK) {
        // commit prefetched tile to smem (A transposed)
        #pragma unroll
        for (int j = 0; j < AF; j++) {
            int i = tid + j * NT;
            int r = i / (BK / 4), cq = i % (BK / 4);
            As[cq * 4 + 0][r] = ra[j].x;
            As[cq * 4 + 1][r] = ra[j].y;
            As[cq * 4 + 2][r] = ra[j].z;
            As[cq * 4 + 3][r] = ra[j].w;
        }
        #pragma unroll
        for (int j = 0; j < BF; j++) {
            int i = tid + j * NT;
            int r = i / (BN / 4), c = i % (BN / 4);
            *(float4*)&Bs[r][c * 4] = rb[j];
        }
        __syncthreads();

        if (kb + BK < kb0 + Kc) { loadA(kb + BK); loadB(kb + BK); }

        // fragment double-buffered FMA loop
        float4 aL = *(const float4*)&As[0][ty * TM];
        float4 aH;
        if (TM == 8) aH = *(const float4*)&As[0][ty * TM + 4];
        float4 bv[TNV];
        #pragma unroll
        for (int c = 0; c < TNV; c++)
            bv[c] = *(const float4*)&Bs[0][c * CST + tx * 4];

        #pragma unroll
        for (int k = 0; k < BK; k++) {
            float4 aLn, aHn, bvn[TNV];
            if (k + 1 < BK) {
                aLn = *(const float4*)&As[k + 1][ty * TM];
                if (TM == 8) aHn = *(const float4*)&As[k + 1][ty * TM + 4];
                #pragma unroll
                for (int c = 0; c < TNV; c++)
                    bvn[c] = *(const float4*)&Bs[k + 1][c * CST + tx * 4];
            }
            ull ap[TMH];
            ap[0] = pack2(aL.x, aL.y);
            ap[1] = pack2(aL.z, aL.w);
            if (TM == 8) { ap[2] = pack2(aH.x, aH.y); ap[3] = pack2(aH.z, aH.w); }
            #pragma unroll
            for (int c = 0; c < TNV; c++) {
                ull b0 = dup2(bv[c].x), b1 = dup2(bv[c].y);
                ull b2 = dup2(bv[c].z), b3 = dup2(bv[c].w);
                #pragma unroll
                for (int i = 0; i < TMH; i++) {
                    fma2(acc[i][c][0], ap[i], b0);
                    fma2(acc[i][c][1], ap[i], b1);
                    fma2(acc[i][c][2], ap[i], b2);
                    fma2(acc[i][c][3], ap[i], b3);
                }
            }
            aL = aLn; if (TM == 8) aH = aHn;
            #pragma unroll
            for (int c = 0; c < TNV; c++) bv[c] = bvn[c];
        }
        __syncthreads();
    }

    // ---- epilogue ----
    float* Cz = Cout + (size_t)blockIdx.z * M * N;
    #pragma unroll
    for (int i = 0; i < TMH; i++) {
        #pragma unroll
        for (int c = 0; c < TNV; c++) {
            int n = bn0 + c * CST + tx * 4;
            if (MASKN && n + 3 >= N) continue;
            float2 v0 = unpack2(acc[i][c][0]);
            float2 v1 = unpack2(acc[i][c][1]);
            float2 v2 = unpack2(acc[i][c][2]);
            float2 v3 = unpack2(acc[i][c][3]);
            int m0 = bm0 + ty * TM + 2 * i;
            float4 o0; o0.x = v0.x; o0.y = v1.x; o0.z = v2.x; o0.w = v3.x;
            float4 o1; o1.x = v0.y; o1.y = v1.y; o1.z = v2.y; o1.w = v3.y;
            *(float4*)&Cz[(size_t)m0 * N + n]       = o0;
            *(float4*)&Cz[(size_t)(m0 + 1) * N + n] = o1;
        }
    }
}

// ---------------- split-K reduction for xproj ----------------
__global__ void reduce_xdbl_kernel()
{
    int i = blockIdx.x * blockDim.x + threadIdx.x;
    const int NV = BL * XDBL_N / 4;   // float4 count
    if (i >= NV) return;
    const float4* p = (const float4*)g_xp;
    float4 s = p[i];
    #pragma unroll
    for (int z = 1; z < XSPLIT; z++) {
        float4 v = p[(size_t)z * NV + i];
        s.x += v.x; s.y += v.y; s.z += v.z; s.w += v.w;
    }
    ((float4*)g_xdbl)[i] = s;
}

// ---------------- causal depthwise conv1d (k=4) + bias + SiLU ----------------
__global__ void conv_silu_kernel(const float* __restrict__ cw,
                                 const float* __restrict__ cb)
{
    int idx = blockIdx.x * blockDim.x + threadIdx.x;
    if (idx >= BL * D4) return;
    int d  = idx & 1023;
    int l  = (idx >> 10) & 1023;
    int bl = idx >> 10;
    float w0 = cw[d * 4], w1 = cw[d * 4 + 1], w2 = cw[d * 4 + 2], w3 = cw[d * 4 + 3];
    const float* xcol = g_xz + d;          // x = first 1024 cols of g_xz
    float acc = cb[d];
    if (l >= 3) acc = fmaf(xcol[(size_t)(bl - 3) * 2048], w0, acc);
    if (l >= 2) acc = fmaf(xcol[(size_t)(bl - 2) * 2048], w1, acc);
    if (l >= 1) acc = fmaf(xcol[(size_t)(bl - 1) * 2048], w2, acc);
    acc = fmaf(xcol[(size_t)bl * 2048], w3, acc);
    float s = 1.f / (1.f + __expf(-acc));
    g_xc[idx] = acc * s;
}

// ---------------- delta = softplus(dlow @ dtproj_W + b) ----------------
__global__ void delta_kernel(const float* __restrict__ dtW,
                             const float* __restrict__ dtb)
{
    int idx = blockIdx.x * blockDim.x + threadIdx.x;
    if (idx >= BL * D4) return;
    int n = idx & 1023;
    int m = idx >> 10;
    const float* xr = g_xdbl + (size_t)m * XDBL_N;
    float acc = dtb[n];
    #pragma unroll
    for (int k = 0; k < DTR; k++)
        acc = fmaf(xr[k], dtW[k * 1024 + n], acc);
    g_dlt[idx] = (acc > 20.f) ? acc : log1pf(__expf(acc));
}

// ---------------- selective scan: smem-staged + shfl butterfly ----------------
#define TC 64
__global__ void __launch_bounds__(128) scan_kernel(
    const float* __restrict__ A_log,
    const float* __restrict__ D_skip)
{
    __shared__ float Bsh[TC][64];
    __shared__ float Csh[TC][64];
    __shared__ float dts[4][TC], xcs[4][TC], zsh[4][TC], ysh[4][TC];

    const int b    = blockIdx.y;
    const int d0   = blockIdx.x * 4;
    const int tid  = threadIdx.x;
    const int wi   = tid >> 5;
    const int lane = tid & 31;
    const int d    = d0 + wi;
    const int n0   = lane << 1;

    const float a0 = -__expf(A_log[d * 64 + n0]);
    const float a1 = -__expf(A_log[d * 64 + n0 + 1]);
    const float Dd = D_skip[d];
    float h0 = 0.f, h1 = 0.f;

    const size_t rbase = (size_t)b * 1024;

    for (int c = 0; c < 1024 / TC; c++) {
        const int t0 = c * TC;
        #pragma unroll 4
        for (int i = tid; i < TC * 32; i += 128) {
            int t = i >> 5, q = i & 31;
            const float* xd = g_xdbl + (rbase + t0 + t) * XDBL_N + DTR;
            float2 bvv = *(const float2*)(xd + 2 * q);
            float2 cvv = *(const float2*)(xd + 64 + 2 * q);
            *(float2*)&Bsh[t][2 * q] = bvv;
            *(float2*)&Csh[t][2 * q] = cvv;
        }
        #pragma unroll 2
        for (int i = tid; i < 4 * TC; i += 128) {
            int t = i >> 2, di = i & 3;
            size_t row = rbase + t0 + t;
            dts[di][t] = g_dlt[row * 1024 + d0 + di];
            xcs[di][t] = g_xc [row * 1024 + d0 + di];
            zsh[di][t] = g_xz [row * 2048 + 1024 + d0 + di];
        }
        __syncthreads();

        #pragma unroll 8
        for (int t = 0; t < TC; t++) {
            float dt = dts[wi][t];
            float xv = xcs[wi][t];
            float2 Bv = *(const float2*)&Bsh[t][n0];
            float2 Cv = *(const float2*)&Csh[t][n0];
            float dx = dt * xv;
            h0 = fmaf(__expf(dt * a0), h0, dx * Bv.x);
            h1 = fmaf(__expf(dt * a1), h1, dx * Bv.y);
            float p = fmaf(h0, Cv.x, h1 * Cv.y);
            p += __shfl_xor_sync(0xffffffffu, p, 16);
            p += __shfl_xor_sync(0xffffffffu, p, 8);
            p += __shfl_xor_sync(0xffffffffu, p, 4);
            p += __shfl_xor_sync(0xffffffffu, p, 2);
            p += __shfl_xor_sync(0xffffffffu, p, 1);
            if (lane == 0) {
                float zv = zsh[wi][t];
                float s  = zv / (1.f + __expf(-zv));
                ysh[wi][t] = (p + xv * Dd) * s;
            }
        }
        __syncthreads();

        #pragma unroll 2
        for (int i = tid; i < 4 * TC; i += 128) {
            int t = i >> 2, di = i & 3;
            g_y[(rbase + t0 + t) * 1024 + d0 + di] = ysh[di][t];
        }
        __syncthreads();
    }
}

// ---------------- launcher ----------------
extern "C" void kernel_launch(void* const* d_in, const int* in_sizes, int n_in,
                              void* d_out, int out_size)
{
    const float* q_r   = (const float*)d_in[0];
    const float* q_i   = (const float*)d_in[1];
    const float* q_j   = (const float*)d_in[2];
    const float* q_k   = (const float*)d_in[3];
    const float* inWr  = (const float*)d_in[4];
    const float* inWi  = (const float*)d_in[5];
    const float* inWj  = (const float*)d_in[6];
    const float* inWk  = (const float*)d_in[7];
    const float* convw = (const float*)d_in[8];
    const float* convb = (const float*)d_in[9];
    const float* xprojW= (const float*)d_in[10];
    const float* dtW   = (const float*)d_in[11];
    const float* dtb   = (const float*)d_in[12];
    const float* A_log = (const float*)d_in[13];
    const float* Dskip = (const float*)d_in[14];
    const float* outWr = (const float*)d_in[15];
    const float* outWi = (const float*)d_in[16];
    const float* outWj = (const float*)d_in[17];
    const float* outWk = (const float*)d_in[18];

    float *xz, *xc, *xp, *yb, *win, *wout;
    cudaGetSymbolAddress((void**)&xz,   g_xz);
    cudaGetSymbolAddress((void**)&xc,   g_xc);
    cudaGetSymbolAddress((void**)&xp,   g_xp);
    cudaGetSymbolAddress((void**)&yb,   g_y);
    cudaGetSymbolAddress((void**)&win,  g_win);
    cudaGetSymbolAddress((void**)&wout, g_wout);

    // 0) expand quaternion weights into plain matrices
    {
        int total = 512 * 2048 + 1024 * 512;
        expand_kernel<<<(total + 255) / 256, 256>>>(
            inWr, inWi, inWj, inWk, outWr, outWi, outWj, outWk);
    }

    // 1) quaternion in_proj: [2048,512] x [512,2048] -> g_xz
    gemm_kernel<true, false, 128, 128, 32, 8, 8, 2><<<dim3(16, 16, 1), 256>>>(
        nullptr, q_r, q_i, q_j, q_k, win, xz, BL, 2048, 512, 512);

    // 2) depthwise conv + bias + SiLU -> g_xc
    conv_silu_kernel<<<(BL * D4) / 256, 256>>>(convw, convb);

    // 3) x_proj split-K=8: [2048,1024] x [1024,136] -> g_xp partials
    gemm_kernel<false, true, 64, 64, 32, 4, 4, 3><<<dim3(3, 32, XSPLIT), 256>>>(
        xc, nullptr, nullptr, nullptr, nullptr, xprojW, xp,
        BL, XDBL_N, 1024, 1024 / XSPLIT);
    reduce_xdbl_kernel<<<(BL * XDBL_N / 4 + 255) / 256, 256>>>();

    // 4) delta = softplus(dlow @ dtW + b) -> g_dlt
    delta_kernel<<<(BL * D4) / 256, 256>>>(dtW, dtb);

    // 5) selective scan + skip + z-gate -> g_y
    scan_kernel<<<dim3(256, BB), 128>>>(A_log, Dskip);

    // 6) quaternion out_proj: [2048,1024] x [1024,512] -> d_out
    gemm_kernel<false, false, 64, 64, 32, 4, 4, 3><<<dim3(8, 32, 1), 256>>>(
        yb, nullptr, nullptr, nullptr, nullptr, wout, (float*)d_out,
        BL, 512, 1024, 1024);
}

// round 6
// speedup vs baseline: 2.5637x; 1.1908x over previous
#include <cuda_runtime.h>
#include <cuda_bf16.h>
#include <cstdint>

typedef unsigned long long ull;

// ---------------- problem constants ----------------
#define BB   2
#define LL   1024
#define D4   1024
#define BL   2048            // BB*LL rows
#define DTR  8
#define XDBL_N 136           // DTR + 2*64
#define XSPLIT 8             // split-K factor for xproj

// ---------------- scratch (static device globals; no allocs) ----------------
__device__ float g_xz  [(size_t)BL * 2048];   // in_proj output: [x(1024) | z(1024)]
__device__ float g_xc  [(size_t)BL * D4];     // conv+silu output
__device__ float g_xdbl[(size_t)BL * XDBL_N]; // x @ xproj_W  -> [dlow(8) | B(64) | C(64)]
__device__ float g_xp  [(size_t)XSPLIT * BL * XDBL_N]; // split-K partials
__device__ float g_dlt [(size_t)BL * D4];     // softplus(dlow@dtW + b)
__device__ float g_y   [(size_t)BL * D4];     // scan output, gated
// bf16-split, TRANSPOSED ([N][K] K-major) quaternion-expanded weights
__device__ __nv_bfloat16 g_winh [(size_t)2048 * 512];
__device__ __nv_bfloat16 g_winl [(size_t)2048 * 512];
__device__ __nv_bfloat16 g_wouth[(size_t)512 * 1024];
__device__ __nv_bfloat16 g_woutl[(size_t)512 * 1024];

// quaternion Hamilton tables: out group g x input group h
__constant__ int   c_qidx[4][4] = {{0,1,2,3},{1,0,3,2},{2,3,0,1},{3,2,1,0}};
__constant__ float c_qsgn[4][4] = {{ 1.f,-1.f,-1.f,-1.f},
                                   { 1.f, 1.f, 1.f,-1.f},
                                   { 1.f,-1.f, 1.f, 1.f},
                                   { 1.f, 1.f,-1.f, 1.f}};

// ---------------- packed f32x2 helpers ----------------
__device__ __forceinline__ ull pack2(float x, float y) {
    ull r; asm("mov.b64 %0, {%1,%2};" : "=l"(r) : "f"(x), "f"(y)); return r;
}
__device__ __forceinline__ ull dup2(float x) {
    ull r; asm("mov.b64 %0, {%1,%1};" : "=l"(r) : "f"(x)); return r;
}
__device__ __forceinline__ float2 unpack2(ull v) {
    float2 r; asm("mov.b64 {%0,%1}, %2;" : "=f"(r.x), "=f"(r.y) : "l"(v)); return r;
}
__device__ __forceinline__ void fma2(ull& d, ull a, ull b) {
    asm("fma.rn.f32x2 %0, %1, %2, %0;" : "+l"(d) : "l"(a), "l"(b));
}

// ---------------- mma.sync m16n8k16 bf16 (arch-neutral tensor path) ----------------
__device__ __forceinline__ void mma16816(float* d, const uint32_t* a, const uint32_t* b) {
    asm volatile(
        "mma.sync.aligned.m16n8k16.row.col.f32.bf16.bf16.f32 "
        "{%0,%1,%2,%3}, {%4,%5,%6,%7}, {%8,%9}, {%0,%1,%2,%3};"
        : "+f"(d[0]), "+f"(d[1]), "+f"(d[2]), "+f"(d[3])
        : "r"(a[0]), "r"(a[1]), "r"(a[2]), "r"(a[3]), "r"(b[0]), "r"(b[1]));
}

// ---------------- weight expansion: quaternion -> transposed bf16 hi/lo ----------------
__global__ void expand_kernel(
    const float* __restrict__ iWr, const float* __restrict__ iWi,
    const float* __restrict__ iWj, const float* __restrict__ iWk,
    const float* __restrict__ oWr, const float* __restrict__ oWi,
    const float* __restrict__ oWj, const float* __restrict__ oWk)
{
    int idx = blockIdx.x * blockDim.x + threadIdx.x;
    const int NIN = 2048 * 512;
    float val;
    if (idx < NIN) {
        int n = idx >> 9, k = idx & 511;
        int g = n >> 9, h = k >> 7;
        int wi = c_qidx[g][h];
        const float* W = (wi == 0) ? iWr : (wi == 1) ? iWi : (wi == 2) ? iWj : iWk;
        val = c_qsgn[g][h] * W[(size_t)(k & 127) * 512 + (n & 511)];
        __nv_bfloat16 hi = __float2bfloat16(val);
        g_winh[idx] = hi;
        g_winl[idx] = __float2bfloat16(val - __bfloat162float(hi));
    } else {
        int j = idx - NIN;
        if (j >= 512 * 1024) return;
        int n = j >> 10, k = j & 1023;
        int g = n >> 7, h = k >> 8;
        int wi = c_qidx[g][h];
        const float* W = (wi == 0) ? oWr : (wi == 1) ? oWi : (wi == 2) ? oWj : oWk;
        val = c_qsgn[g][h] * W[(size_t)(k & 255) * 128 + (n & 127)];
        __nv_bfloat16 hi = __float2bfloat16(val);
        g_wouth[j] = hi;
        g_woutl[j] = __float2bfloat16(val - __bfloat162float(hi));
    }
}

// ---------------- tensor-core GEMM via mma.sync, bf16-split ----------------
// C[M,N] = A[M,K] (fp32, converted in-kernel) x B[N,K]^T (bf16 hi/lo)
// QA: A = concat(q_r,q_i,q_j,q_k) along K (each [M,128])
// 256 threads = 8 warps laid out WM x WN; BK = 32.
template<bool QA, int BM, int BN, int WM, int WN>
__global__ void __launch_bounds__(256, 1) mma_gemm(
    const float* __restrict__ A,
    const float* __restrict__ Q0, const float* __restrict__ Q1,
    const float* __restrict__ Q2, const float* __restrict__ Q3,
    const __nv_bfloat16* __restrict__ Bh, const __nv_bfloat16* __restrict__ Bl,
    float* __restrict__ C, int M, int N, int K)
{
    constexpr int BK  = 32;
    constexpr int STR = 40;                 // smem row stride (bf16 elems)
    constexpr int WTM = BM / WM, WTN = BN / WN;
    constexpr int MT  = WTM / 16, NT = WTN / 8;
    constexpr int AF  = BM * BK / (256 * 4);    // float4 A-loads / thread
    constexpr int BF  = BN * BK / (256 * 8);    // uint4 B-loads / thread / split
    static_assert(WM * WN == 8, "8 warps");

    __shared__ __nv_bfloat16 Ah[BM][STR], Al[BM][STR];
    __shared__ __nv_bfloat16 Bsh[BN][STR], Bsl[BN][STR];

    const int tid  = threadIdx.x;
    const int wid  = tid >> 5;
    const int lane = tid & 31;
    const int wm   = wid % WM, wn = wid / WM;
    const int bn0  = blockIdx.x * BN;
    const int bm0  = blockIdx.y * BM;
    const int m_base = wm * WTM;
    const int n_base = wn * WTN;

    float acc[MT][NT][4];
    #pragma unroll
    for (int i = 0; i < MT; i++)
        #pragma unroll
        for (int j = 0; j < NT; j++)
            #pragma unroll
            for (int q = 0; q < 4; q++) acc[i][j][q] = 0.f;

    float4 ra[AF];
    uint4  rbh[BF], rbl[BF];

    auto loadA = [&](int kb) {
        #pragma unroll
        for (int j = 0; j < AF; j++) {
            int i = tid + j * 256;
            int r = i >> 3, c4 = i & 7;              // row, float4-chunk (8 per row)
            const float* src;
            if (QA) {
                const float* q = ((kb >> 7) == 0) ? Q0 : ((kb >> 7) == 1) ? Q1
                               : ((kb >> 7) == 2) ? Q2 : Q3;
                src = q + (size_t)(bm0 + r) * 128 + (kb & 127) + c4 * 4;
            } else {
                src = A + (size_t)(bm0 + r) * K + kb + c4 * 4;
            }
            ra[j] = *(const float4*)src;
        }
    };
    auto loadB = [&](int kb) {
        #pragma unroll
        for (int j = 0; j < BF; j++) {
            int i = tid + j * 256;
            int n = i >> 2, c = i & 3;               // row, uint4-chunk (4 per row)
            const size_t go = (size_t)(bn0 + n) * K + kb + c * 8;
            rbh[j] = *(const uint4*)(Bh + go);
            rbl[j] = *(const uint4*)(Bl + go);
        }
    };

    loadA(0); loadB(0);

    for (int kb = 0; kb < K; kb += BK) {
        // ---- commit registers -> smem (A: fp32 -> bf16 hi/lo) ----
        #pragma unroll
        for (int j = 0; j < AF; j++) {
            int i = tid + j * 256;
            int r = i >> 3, c4 = i & 7;
            float4 a = ra[j];
            __nv_bfloat16 hx = __float2bfloat16(a.x), hy = __float2bfloat16(a.y);
            __nv_bfloat16 hz = __float2bfloat16(a.z), hw = __float2bfloat16(a.w);
            __nv_bfloat162 h01 = __halves2bfloat162(hx, hy);
            __nv_bfloat162 h23 = __halves2bfloat162(hz, hw);
            __nv_bfloat162 l01 = __floats2bfloat162_rn(a.x - __bfloat162float(hx),
                                                       a.y - __bfloat162float(hy));
            __nv_bfloat162 l23 = __floats2bfloat162_rn(a.z - __bfloat162float(hz),
                                                       a.w - __bfloat162float(hw));
            *(uint32_t*)&Ah[r][c4 * 4]     = *(uint32_t*)&h01;
            *(uint32_t*)&Ah[r][c4 * 4 + 2] = *(uint32_t*)&h23;
            *(uint32_t*)&Al[r][c4 * 4]     = *(uint32_t*)&l01;
            *(uint32_t*)&Al[r][c4 * 4 + 2] = *(uint32_t*)&l23;
        }
        #pragma unroll
        for (int j = 0; j < BF; j++) {
            int i = tid + j * 256;
            int n = i >> 2, c = i & 3;
            *(uint4*)&Bsh[n][c * 8] = rbh[j];
            *(uint4*)&Bsl[n][c * 8] = rbl[j];
        }
        __syncthreads();

        if (kb + BK < K) { loadA(kb + BK); loadB(kb + BK); }

        // ---- two k16 steps of mma over the smem tile ----
        #pragma unroll
        for (int kk = 0; kk < BK; kk += 16) {
            uint32_t afh[MT][4], afl[MT][4];
            const int kf = kk + (lane & 3) * 2;
            #pragma unroll
            for (int mi = 0; mi < MT; mi++) {
                int m = m_base + mi * 16 + (lane >> 2);
                afh[mi][0] = *(const uint32_t*)&Ah[m][kf];
                afh[mi][1] = *(const uint32_t*)&Ah[m + 8][kf];
                afh[mi][2] = *(const uint32_t*)&Ah[m][kf + 8];
                afh[mi][3] = *(const uint32_t*)&Ah[m + 8][kf + 8];
                afl[mi][0] = *(const uint32_t*)&Al[m][kf];
                afl[mi][1] = *(const uint32_t*)&Al[m + 8][kf];
                afl[mi][2] = *(const uint32_t*)&Al[m][kf + 8];
                afl[mi][3] = *(const uint32_t*)&Al[m + 8][kf + 8];
            }
            uint32_t bfh[NT][2], bfl[NT][2];
            #pragma unroll
            for (int ni = 0; ni < NT; ni++) {
                int n = n_base + ni * 8 + (lane >> 2);
                bfh[ni][0] = *(const uint32_t*)&Bsh[n][kf];
                bfh[ni][1] = *(const uint32_t*)&Bsh[n][kf + 8];
                bfl[ni][0] = *(const uint32_t*)&Bsl[n][kf];
                bfl[ni][1] = *(const uint32_t*)&Bsl[n][kf + 8];
            }
            #pragma unroll
            for (int mi = 0; mi < MT; mi++)
                #pragma unroll
                for (int ni = 0; ni < NT; ni++) {
                    mma16816(acc[mi][ni], afh[mi], bfh[ni]);
                    mma16816(acc[mi][ni], afh[mi], bfl[ni]);
                    mma16816(acc[mi][ni], afl[mi], bfh[ni]);
                }
        }
        __syncthreads();
    }

    // ---- epilogue ----
    #pragma unroll
    for (int mi = 0; mi < MT; mi++) {
        #pragma unroll
        for (int ni = 0; ni < NT; ni++) {
            int r = bm0 + m_base + mi * 16 + (lane >> 2);
            int c = bn0 + n_base + ni * 8 + (lane & 3) * 2;
            *(float2*)&C[(size_t)r * N + c]       = make_float2(acc[mi][ni][0], acc[mi][ni][1]);
            *(float2*)&C[(size_t)(r + 8) * N + c] = make_float2(acc[mi][ni][2], acc[mi][ni][3]);
        }
    }
}

// ---------------- fp32 tiled GEMM (xproj split-K only) ----------------
template<bool MASKN, int BM, int BN, int BK, int TM, int TN, int NB>
__global__ void __launch_bounds__(256, NB) gemm_kernel(
    const float* __restrict__ A, const float* __restrict__ Bm,
    float* __restrict__ Cout, int M, int N, int K, int Kc)
{
    constexpr int NT  = 256;
    static_assert((BM / TM) * (BN / TN) == NT, "thread count");
    constexpr int TMH = TM / 2;
    constexpr int TNV = TN / 4;
    constexpr int CST = BN / TNV;
    constexpr int AF  = BM * BK / (NT * 4);
    constexpr int BF  = BK * BN / (NT * 4);

    __shared__ float As[BK][BM + 4];
    __shared__ float Bs[BK][BN + 4];

    const int tid = threadIdx.x;
    const int bn0 = blockIdx.x * BN;
    const int bm0 = blockIdx.y * BM;
    const int kb0 = blockIdx.z * Kc;
    const int tx  = tid % (BN / TN);
    const int ty  = tid / (BN / TN);

    ull acc[TMH][TNV][4];
    #pragma unroll
    for (int i = 0; i < TMH; i++)
        #pragma unroll
        for (int c = 0; c < TNV; c++)
            #pragma unroll
            for (int j = 0; j < 4; j++) acc[i][c][j] = 0ull;

    float4 ra[AF], rb[BF];

    auto loadA = [&](int kb) {
        #pragma unroll
        for (int j = 0; j < AF; j++) {
            int i = tid + j * NT;
            int r = i / (BK / 4), cq = i % (BK / 4);
            ra[j] = *(const float4*)(A + (size_t)(bm0 + r) * K + kb + cq * 4);
        }
    };
    auto loadB = [&](int kb) {
        #pragma unroll
        for (int j = 0; j < BF; j++) {
            int i = tid + j * NT;
            int r = i / (BN / 4), c = i % (BN / 4);
            int n = bn0 + c * 4;
            if (MASKN && n + 3 >= N) rb[j] = make_float4(0.f, 0.f, 0.f, 0.f);
            else rb[j] = *(const float4*)(Bm + (size_t)(kb + r) * N + n);
        }
    };

    loadA(kb0); loadB(kb0);

    for (int kb = kb0; kb < kb0 + Kc; kb += BK) {
        #pragma unroll
        for (int j = 0; j < AF; j++) {
            int i = tid + j * NT;
            int r = i / (BK / 4), cq = i % (BK / 4);
            As[cq * 4 + 0][r] = ra[j].x;
            As[cq * 4 + 1][r] = ra[j].y;
            As[cq * 4 + 2][r] = ra[j].z;
            As[cq * 4 + 3][r] = ra[j].w;
        }
        #pragma unroll
        for (int j = 0; j < BF; j++) {
            int i = tid + j * NT;
            int r = i / (BN / 4), c = i % (BN / 4);
            *(float4*)&Bs[r][c * 4] = rb[j];
        }
        __syncthreads();

        if (kb + BK < kb0 + Kc) { loadA(kb + BK); loadB(kb + BK); }

        float4 aL = *(const float4*)&As[0][ty * TM];
        float4 bv[TNV];
        #pragma unroll
        for (int c = 0; c < TNV; c++)
            bv[c] = *(const float4*)&Bs[0][c * CST + tx * 4];

        #pragma unroll
        for (int k = 0; k < BK; k++) {
            float4 aLn, bvn[TNV];
            if (k + 1 < BK) {
                aLn = *(const float4*)&As[k + 1][ty * TM];
                #pragma unroll
                for (int c = 0; c < TNV; c++)
                    bvn[c] = *(const float4*)&Bs[k + 1][c * CST + tx * 4];
            }
            ull ap[TMH];
            ap[0] = pack2(aL.x, aL.y);
            ap[1] = pack2(aL.z, aL.w);
            #pragma unroll
            for (int c = 0; c < TNV; c++) {
                ull b0 = dup2(bv[c].x), b1 = dup2(bv[c].y);
                ull b2 = dup2(bv[c].z), b3 = dup2(bv[c].w);
                #pragma unroll
                for (int i = 0; i < TMH; i++) {
                    fma2(acc[i][c][0], ap[i], b0);
                    fma2(acc[i][c][1], ap[i], b1);
                    fma2(acc[i][c][2], ap[i], b2);
                    fma2(acc[i][c][3], ap[i], b3);
                }
            }
            aL = aLn;
            #pragma unroll
            for (int c = 0; c < TNV; c++) bv[c] = bvn[c];
        }
        __syncthreads();
    }

    float* Cz = Cout + (size_t)blockIdx.z * M * N;
    #pragma unroll
    for (int i = 0; i < TMH; i++) {
        #pragma unroll
        for (int c = 0; c < TNV; c++) {
            int n = bn0 + c * CST + tx * 4;
            if (MASKN && n + 3 >= N) continue;
            float2 v0 = unpack2(acc[i][c][0]);
            float2 v1 = unpack2(acc[i][c][1]);
            float2 v2 = unpack2(acc[i][c][2]);
            float2 v3 = unpack2(acc[i][c][3]);
            int m0 = bm0 + ty * TM + 2 * i;
            float4 o0; o0.x = v0.x; o0.y = v1.x; o0.z = v2.x; o0.w = v3.x;
            float4 o1; o1.x = v0.y; o1.y = v1.y; o1.z = v2.y; o1.w = v3.y;
            *(float4*)&Cz[(size_t)m0 * N + n]       = o0;
            *(float4*)&Cz[(size_t)(m0 + 1) * N + n] = o1;
        }
    }
}

// ---------------- split-K reduction for xproj ----------------
__global__ void reduce_xdbl_kernel()
{
    int i = blockIdx.x * blockDim.x + threadIdx.x;
    const int NV = BL * XDBL_N / 4;
    if (i >= NV) return;
    const float4* p = (const float4*)g_xp;
    float4 s = p[i];
    #pragma unroll
    for (int z = 1; z < XSPLIT; z++) {
        float4 v = p[(size_t)z * NV + i];
        s.x += v.x; s.y += v.y; s.z += v.z; s.w += v.w;
    }
    ((float4*)g_xdbl)[i] = s;
}

// ---------------- causal depthwise conv1d (k=4) + bias + SiLU ----------------
__global__ void conv_silu_kernel(const float* __restrict__ cw,
                                 const float* __restrict__ cb)
{
    int idx = blockIdx.x * blockDim.x + threadIdx.x;
    if (idx >= BL * D4) return;
    int d  = idx & 1023;
    int l  = (idx >> 10) & 1023;
    int bl = idx >> 10;
    float w0 = cw[d * 4], w1 = cw[d * 4 + 1], w2 = cw[d * 4 + 2], w3 = cw[d * 4 + 3];
    const float* xcol = g_xz + d;
    float acc = cb[d];
    if (l >= 3) acc = fmaf(xcol[(size_t)(bl - 3) * 2048], w0, acc);
    if (l >= 2) acc = fmaf(xcol[(size_t)(bl - 2) * 2048], w1, acc);
    if (l >= 1) acc = fmaf(xcol[(size_t)(bl - 1) * 2048], w2, acc);
    acc = fmaf(xcol[(size_t)bl * 2048], w3, acc);
    float s = 1.f / (1.f + __expf(-acc));
    g_xc[idx] = acc * s;
}

// ---------------- delta = softplus(dlow @ dtproj_W + b) ----------------
__global__ void delta_kernel(const float* __restrict__ dtW,
                             const float* __restrict__ dtb)
{
    int idx = blockIdx.x * blockDim.x + threadIdx.x;
    if (idx >= BL * D4) return;
    int n = idx & 1023;
    int m = idx >> 10;
    const float* xr = g_xdbl + (size_t)m * XDBL_N;
    float acc = dtb[n];
    #pragma unroll
    for (int k = 0; k < DTR; k++)
        acc = fmaf(xr[k], dtW[k * 1024 + n], acc);
    g_dlt[idx] = (acc > 20.f) ? acc : log1pf(__expf(acc));
}

// ---------------- selective scan: smem-staged + shfl butterfly ----------------
#define TC 64
__global__ void __launch_bounds__(128) scan_kernel(
    const float* __restrict__ A_log,
    const float* __restrict__ D_skip)
{
    __shared__ float Bsh[TC][64];
    __shared__ float Csh[TC][64];
    __shared__ float dts[4][TC], xcs[4][TC], zsh[4][TC], ysh[4][TC];

    const int b    = blockIdx.y;
    const int d0   = blockIdx.x * 4;
    const int tid  = threadIdx.x;
    const int wi   = tid >> 5;
    const int lane = tid & 31;
    const int d    = d0 + wi;
    const int n0   = lane << 1;

    const float a0 = -__expf(A_log[d * 64 + n0]);
    const float a1 = -__expf(A_log[d * 64 + n0 + 1]);
    const float Dd = D_skip[d];
    float h0 = 0.f, h1 = 0.f;

    const size_t rbase = (size_t)b * 1024;

    for (int c = 0; c < 1024 / TC; c++) {
        const int t0 = c * TC;
        #pragma unroll 4
        for (int i = tid; i < TC * 32; i += 128) {
            int t = i >> 5, q = i & 31;
            const float* xd = g_xdbl + (rbase + t0 + t) * XDBL_N + DTR;
            float2 bvv = *(const float2*)(xd + 2 * q);
            float2 cvv = *(const float2*)(xd + 64 + 2 * q);
            *(float2*)&Bsh[t][2 * q] = bvv;
            *(float2*)&Csh[t][2 * q] = cvv;
        }
        #pragma unroll 2
        for (int i = tid; i < 4 * TC; i += 128) {
            int t = i >> 2, di = i & 3;
            size_t row = rbase + t0 + t;
            dts[di][t] = g_dlt[row * 1024 + d0 + di];
            xcs[di][t] = g_xc [row * 1024 + d0 + di];
            zsh[di][t] = g_xz [row * 2048 + 1024 + d0 + di];
        }
        __syncthreads();

        #pragma unroll 8
        for (int t = 0; t < TC; t++) {
            float dt = dts[wi][t];
            float xv = xcs[wi][t];
            float2 Bv = *(const float2*)&Bsh[t][n0];
            float2 Cv = *(const float2*)&Csh[t][n0];
            float dx = dt * xv;
            h0 = fmaf(__expf(dt * a0), h0, dx * Bv.x);
            h1 = fmaf(__expf(dt * a1), h1, dx * Bv.y);
            float p = fmaf(h0, Cv.x, h1 * Cv.y);
            p += __shfl_xor_sync(0xffffffffu, p, 16);
            p += __shfl_xor_sync(0xffffffffu, p, 8);
            p += __shfl_xor_sync(0xffffffffu, p, 4);
            p += __shfl_xor_sync(0xffffffffu, p, 2);
            p += __shfl_xor_sync(0xffffffffu, p, 1);
            if (lane == 0) {
                float zv = zsh[wi][t];
                float s  = zv / (1.f + __expf(-zv));
                ysh[wi][t] = (p + xv * Dd) * s;
            }
        }
        __syncthreads();

        #pragma unroll 2
        for (int i = tid; i < 4 * TC; i += 128) {
            int t = i >> 2, di = i & 3;
            g_y[(rbase + t0 + t) * 1024 + d0 + di] = ysh[di][t];
        }
        __syncthreads();
    }
}

// ---------------- launcher ----------------
extern "C" void kernel_launch(void* const* d_in, const int* in_sizes, int n_in,
                              void* d_out, int out_size)
{
    const float* q_r   = (const float*)d_in[0];
    const float* q_i   = (const float*)d_in[1];
    const float* q_j   = (const float*)d_in[2];
    const float* q_k   = (const float*)d_in[3];
    const float* inWr  = (const float*)d_in[4];
    const float* inWi  = (const float*)d_in[5];
    const float* inWj  = (const float*)d_in[6];
    const float* inWk  = (const float*)d_in[7];
    const float* convw = (const float*)d_in[8];
    const float* convb = (const float*)d_in[9];
    const float* xprojW= (const float*)d_in[10];
    const float* dtW   = (const float*)d_in[11];
    const float* dtb   = (const float*)d_in[12];
    const float* A_log = (const float*)d_in[13];
    const float* Dskip = (const float*)d_in[14];
    const float* outWr = (const float*)d_in[15];
    const float* outWi = (const float*)d_in[16];
    const float* outWj = (const float*)d_in[17];
    const float* outWk = (const float*)d_in[18];

    float *xz, *xc, *xp, *yb;
    __nv_bfloat16 *winh, *winl, *wouth, *woutl;
    cudaGetSymbolAddress((void**)&xz,    g_xz);
    cudaGetSymbolAddress((void**)&xc,    g_xc);
    cudaGetSymbolAddress((void**)&xp,    g_xp);
    cudaGetSymbolAddress((void**)&yb,    g_y);
    cudaGetSymbolAddress((void**)&winh,  g_winh);
    cudaGetSymbolAddress((void**)&winl,  g_winl);
    cudaGetSymbolAddress((void**)&wouth, g_wouth);
    cudaGetSymbolAddress((void**)&woutl, g_woutl);

    // 0) expand quaternion weights -> transposed bf16 hi/lo
    {
        int total = 2048 * 512 + 512 * 1024;
        expand_kernel<<<(total + 255) / 256, 256>>>(
            inWr, inWi, inWj, inWk, outWr, outWi, outWj, outWk);
    }

    // 1) in_proj (mma.sync bf16-split): [2048,512] x [512,2048] -> g_xz
    mma_gemm<true, 128, 128, 2, 4><<<dim3(16, 16), 256>>>(
        nullptr, q_r, q_i, q_j, q_k, winh, winl, xz, BL, 2048, 512);

    // 2) depthwise conv + bias + SiLU -> g_xc
    conv_silu_kernel<<<(BL * D4) / 256, 256>>>(convw, convb);

    // 3) x_proj split-K=8 (fp32): [2048,1024] x [1024,136] -> partials -> g_xdbl
    gemm_kernel<true, 64, 64, 32, 4, 4, 3><<<dim3(3, 32, XSPLIT), 256>>>(
        xc, xprojW, xp, BL, XDBL_N, 1024, 1024 / XSPLIT);
    reduce_xdbl_kernel<<<(BL * XDBL_N / 4 + 255) / 256, 256>>>();

    // 4) delta = softplus(dlow @ dtW + b) -> g_dlt
    delta_kernel<<<(BL * D4) / 256, 256>>>(dtW, dtb);

    // 5) selective scan + skip + z-gate -> g_y
    scan_kernel<<<dim3(256, BB), 128>>>(A_log, Dskip);

    // 6) out_proj (mma.sync bf16-split): [2048,1024] x [1024,512] -> d_out
    mma_gemm<false, 128, 64, 4, 2><<<dim3(8, 16), 256>>>(
        yb, nullptr, nullptr, nullptr, nullptr, wouth, woutl,
        (float*)d_out, BL, 512, 1024);
}

// round 7
// speedup vs baseline: 2.7791x; 1.0840x over previous
#include <cuda_runtime.h>
#include <cuda_bf16.h>
#include <cstdint>

typedef unsigned long long ull;
typedef __nv_bfloat16 bf16;

// ---------------- problem constants ----------------
#define BB   2
#define LL   1024
#define D4   1024
#define BL   2048            // BB*LL rows
#define DTR  8
#define XDBL_N 136           // DTR + 2*64
#define XN_PAD 192           // padded xproj N for 64-wide tiles

// ---------------- scratch (static device globals; no allocs) ----------------
__device__ float g_xz  [(size_t)BL * 2048];
__device__ float g_xc  [(size_t)BL * D4];
__device__ float g_xdbl[(size_t)BL * XDBL_N];
__device__ float g_xp  [(size_t)8 * BL * XDBL_N];   // split-K partials (shared scratch)
__device__ float g_dlt [(size_t)BL * D4];
__device__ float g_y   [(size_t)BL * D4];
// bf16-split transposed weights ([N][K], K-major)
__device__ bf16 g_winh [(size_t)2048 * 512],  g_winl [(size_t)2048 * 512];
__device__ bf16 g_wouth[(size_t)512 * 1024],  g_woutl[(size_t)512 * 1024];
__device__ bf16 g_xpwh [(size_t)XN_PAD * 1024], g_xpwl[(size_t)XN_PAD * 1024];
// bf16-split activations
__device__ bf16 g_ah [(size_t)BL * 512],  g_al [(size_t)BL * 512];
__device__ bf16 g_xch[(size_t)BL * 1024], g_xcl[(size_t)BL * 1024];
__device__ bf16 g_yh [(size_t)BL * 1024], g_yl [(size_t)BL * 1024];

// quaternion Hamilton tables
__constant__ int   c_qidx[4][4] = {{0,1,2,3},{1,0,3,2},{2,3,0,1},{3,2,1,0}};
__constant__ float c_qsgn[4][4] = {{ 1.f,-1.f,-1.f,-1.f},
                                   { 1.f, 1.f, 1.f,-1.f},
                                   { 1.f,-1.f, 1.f, 1.f},
                                   { 1.f, 1.f,-1.f, 1.f}};

// ---------------- ptx helpers (all sm_80-era, sm_103-legal) ----------------
__device__ __forceinline__ uint32_t smem_u32(const void* p) {
    uint32_t a;
    asm("{ .reg .u64 t; cvta.to.shared.u64 t, %1; cvt.u32.u64 %0, t; }" : "=r"(a) : "l"(p));
    return a;
}
__device__ __forceinline__ void cpa16(uint32_t s, const void* g) {
    asm volatile("cp.async.cg.shared.global [%0], [%1], 16;" :: "r"(s), "l"(g));
}
#define CP_COMMIT() asm volatile("cp.async.commit_group;" ::: "memory")
#define CP_WAIT1()  asm volatile("cp.async.wait_group 1;"  ::: "memory")
#define CP_WAIT0()  asm volatile("cp.async.wait_group 0;"  ::: "memory")
#define LDSM4(R, a) \
    asm volatile("ldmatrix.sync.aligned.m8n8.x4.shared.b16 {%0,%1,%2,%3}, [%4];" \
        : "=r"((R)[0]), "=r"((R)[1]), "=r"((R)[2]), "=r"((R)[3]) : "r"(a))

__device__ __forceinline__ void mma16816(float* d, const uint32_t* a, const uint32_t* b) {
    asm volatile(
        "mma.sync.aligned.m16n8k16.row.col.f32.bf16.bf16.f32 "
        "{%0,%1,%2,%3}, {%4,%5,%6,%7}, {%8,%9}, {%0,%1,%2,%3};"
        : "+f"(d[0]), "+f"(d[1]), "+f"(d[2]), "+f"(d[3])
        : "r"(a[0]), "r"(a[1]), "r"(a[2]), "r"(a[3]), "r"(b[0]), "r"(b[1]));
}

__device__ __forceinline__ void split4(float4 v, uint2& ho, uint2& lo) {
    bf16 hx = __float2bfloat16(v.x), hy = __float2bfloat16(v.y);
    bf16 hz = __float2bfloat16(v.z), hw = __float2bfloat16(v.w);
    __nv_bfloat162 h01 = __halves2bfloat162(hx, hy);
    __nv_bfloat162 h23 = __halves2bfloat162(hz, hw);
    __nv_bfloat162 l01 = __floats2bfloat162_rn(v.x - __bfloat162float(hx),
                                               v.y - __bfloat162float(hy));
    __nv_bfloat162 l23 = __floats2bfloat162_rn(v.z - __bfloat162float(hz),
                                               v.w - __bfloat162float(hw));
    ho = make_uint2(*(uint32_t*)&h01, *(uint32_t*)&h23);
    lo = make_uint2(*(uint32_t*)&l01, *(uint32_t*)&l23);
}

// ---------------- weight expansion: quaternion + xproj -> transposed bf16 hi/lo ----
__global__ void expand_kernel(
    const float* __restrict__ iWr, const float* __restrict__ iWi,
    const float* __restrict__ iWj, const float* __restrict__ iWk,
    const float* __restrict__ oWr, const float* __restrict__ oWi,
    const float* __restrict__ oWj, const float* __restrict__ oWk,
    const float* __restrict__ xpW)
{
    int idx = blockIdx.x * blockDim.x + threadIdx.x;
    const int NIN = 2048 * 512;
    const int NOUT = 512 * 1024;
    float val;
    if (idx < NIN) {
        int n = idx >> 9, k = idx & 511;
        int g = n >> 9, h = k >> 7;
        int wi = c_qidx[g][h];
        const float* W = (wi == 0) ? iWr : (wi == 1) ? iWi : (wi == 2) ? iWj : iWk;
        val = c_qsgn[g][h] * W[(size_t)(k & 127) * 512 + (n & 511)];
        bf16 hi = __float2bfloat16(val);
        g_winh[idx] = hi;
        g_winl[idx] = __float2bfloat16(val - __bfloat162float(hi));
    } else if (idx < NIN + NOUT) {
        int j = idx - NIN;
        int n = j >> 10, k = j & 1023;
        int g = n >> 7, h = k >> 8;
        int wi = c_qidx[g][h];
        const float* W = (wi == 0) ? oWr : (wi == 1) ? oWi : (wi == 2) ? oWj : oWk;
        val = c_qsgn[g][h] * W[(size_t)(k & 255) * 128 + (n & 127)];
        bf16 hi = __float2bfloat16(val);
        g_wouth[j] = hi;
        g_woutl[j] = __float2bfloat16(val - __bfloat162float(hi));
    } else {
        int j = idx - NIN - NOUT;
        if (j >= XN_PAD * 1024) return;
        int n = j >> 10, k = j & 1023;
        val = (n < XDBL_N) ? xpW[(size_t)k * XDBL_N + n] : 0.f;
        bf16 hi = __float2bfloat16(val);
        g_xpwh[j] = hi;
        g_xpwl[j] = __float2bfloat16(val - __bfloat162float(hi));
    }
}

// ---------------- activation bf16-splits ----------------
__global__ void qsplit_kernel(const float* __restrict__ Q0, const float* __restrict__ Q1,
                              const float* __restrict__ Q2, const float* __restrict__ Q3)
{
    int i = blockIdx.x * blockDim.x + threadIdx.x;   // over 2048*512/4 float4
    if (i >= BL * 512 / 4) return;
    int m = i >> 7, c4 = i & 127;
    int k = c4 * 4;
    const float* q = (k < 128) ? Q0 : (k < 256) ? Q1 : (k < 384) ? Q2 : Q3;
    float4 v = *(const float4*)(q + (size_t)m * 128 + (k & 127));
    uint2 h, l; split4(v, h, l);
    ((uint2*)g_ah)[i] = h;
    ((uint2*)g_al)[i] = l;
}
__global__ void fsplit_kernel(const float4* __restrict__ src,
                              bf16* __restrict__ h, bf16* __restrict__ l, int n4)
{
    int i = blockIdx.x * blockDim.x + threadIdx.x;
    if (i >= n4) return;
    uint2 ho, lo; split4(src[i], ho, lo);
    ((uint2*)h)[i] = ho;
    ((uint2*)l)[i] = lo;
}

// ---------------- mma GEMM: bf16-split, cp.async 2-stage, ldmatrix ----------------
// C(+z partial)[M,Nout] = A[M,K] x B[N,K]^T ; BM=128, BN=64, BK=64, 256 thr
#define GSTG 49152
#define GSMEM (2 * GSTG)
template<bool MASKN>
__global__ void __launch_bounds__(256, 2) mma_gemm(
    const bf16* __restrict__ Ah_g, const bf16* __restrict__ Al_g,
    const bf16* __restrict__ Bh_g, const bf16* __restrict__ Bl_g,
    float* __restrict__ C, int M, int K, int Kc, int Nout)
{
    extern __shared__ char smx[];
    const uint32_t sb = smem_u32(smx);
    const int OFF_AL = 16384, OFF_BH = 32768, OFF_BL = 40960;

    const int tid  = threadIdx.x;
    const int wid  = tid >> 5;
    const int lane = tid & 31;
    const int wm   = wid & 3;            // 4 warps along M
    const int wn   = wid >> 2;           // 2 along N
    const int bn0  = blockIdx.x * 64;
    const int bm0  = blockIdx.y * 128;
    const int kb0  = blockIdx.z * Kc;
    const int m_base = wm * 32;
    const int n_base = wn * 32;

    float acc[2][4][4];
    #pragma unroll
    for (int i = 0; i < 2; i++)
        #pragma unroll
        for (int j = 0; j < 4; j++)
            #pragma unroll
            for (int q = 0; q < 4; q++) acc[i][j][q] = 0.f;

    auto issue = [&](int s, int kb) {
        uint32_t st = sb + (s & 1) * GSTG;
        #pragma unroll
        for (int it = 0; it < 4; it++) {          // A: 1024 hi chunks + 1024 lo
            int c = tid + it * 256;
            int r = c >> 3, ch = c & 7;
            uint32_t so = st + r * 128 + ((ch ^ (r & 7)) << 4);
            const size_t go = (size_t)(bm0 + r) * K + kb + ch * 8;
            cpa16(so,           Ah_g + go);
            cpa16(so + OFF_AL,  Al_g + go);
        }
        #pragma unroll
        for (int it = 0; it < 2; it++) {          // B: 512 hi + 512 lo
            int c = tid + it * 256;
            int r = c >> 3, ch = c & 7;
            uint32_t so = st + OFF_BH + r * 128 + ((ch ^ (r & 7)) << 4);
            const size_t go = (size_t)(bn0 + r) * K + kb + ch * 8;
            cpa16(so,                     Bh_g + go);
            cpa16(so + (OFF_BL - OFF_BH), Bl_g + go);
        }
        CP_COMMIT();
    };

    const int ntiles = Kc >> 6;
    issue(0, kb0);

    for (int s = 0; s < ntiles; s++) {
        if (s + 1 < ntiles) { issue(s + 1, kb0 + (s + 1) * 64); CP_WAIT1(); }
        else                { CP_WAIT0(); }
        __syncthreads();
        uint32_t st = sb + (s & 1) * GSTG;

        #pragma unroll
        for (int kk = 0; kk < 64; kk += 16) {
            uint32_t ah[2][4], al[2][4];
            #pragma unroll
            for (int mi = 0; mi < 2; mi++) {
                int m  = m_base + mi * 16 + (lane & 15);
                int kc = (kk >> 3) + (lane >> 4);
                uint32_t ad = st + m * 128 + (((kc) ^ (m & 7)) << 4);
                LDSM4(ah[mi], ad);
                LDSM4(al[mi], ad + OFF_AL);
            }
            uint32_t bh[4][2], bl[4][2];
            #pragma unroll
            for (int nj = 0; nj < 2; nj++) {
                int n  = n_base + nj * 16 + (lane & 7) + ((lane >> 4) << 3);
                int kc = (kk >> 3) + ((lane >> 3) & 1);
                uint32_t bd = st + OFF_BH + n * 128 + (((kc) ^ (n & 7)) << 4);
                uint32_t rh[4], rl[4];
                LDSM4(rh, bd);
                LDSM4(rl, bd + (OFF_BL - OFF_BH));
                bh[2*nj][0] = rh[0]; bh[2*nj][1] = rh[1];
                bh[2*nj+1][0] = rh[2]; bh[2*nj+1][1] = rh[3];
                bl[2*nj][0] = rl[0]; bl[2*nj][1] = rl[1];
                bl[2*nj+1][0] = rl[2]; bl[2*nj+1][1] = rl[3];
            }
            #pragma unroll
            for (int mi = 0; mi < 2; mi++)
                #pragma unroll
                for (int ni = 0; ni < 4; ni++) {
                    mma16816(acc[mi][ni], ah[mi], bh[ni]);
                    mma16816(acc[mi][ni], ah[mi], bl[ni]);
                    mma16816(acc[mi][ni], al[mi], bh[ni]);
                }
        }
        __syncthreads();
    }

    // ---- epilogue ----
    float* Cz = C + (size_t)blockIdx.z * M * Nout;
    #pragma unroll
    for (int mi = 0; mi < 2; mi++) {
        #pragma unroll
        for (int ni = 0; ni < 4; ni++) {
            int r = bm0 + m_base + mi * 16 + (lane >> 2);
            int c = bn0 + n_base + ni * 8 + (lane & 3) * 2;
            if (MASKN && c >= Nout) continue;
            *(float2*)&Cz[(size_t)r * Nout + c] =
                make_float2(acc[mi][ni][0], acc[mi][ni][1]);
            *(float2*)&Cz[(size_t)(r + 8) * Nout + c] =
                make_float2(acc[mi][ni][2], acc[mi][ni][3]);
        }
    }
}

// ---------------- generic split-K reduction ----------------
__global__ void reduce_kernel(const float4* __restrict__ src, float4* __restrict__ dst,
                              int nv4, int nsl)
{
    int i = blockIdx.x * blockDim.x + threadIdx.x;
    if (i >= nv4) return;
    float4 s = src[i];
    for (int z = 1; z < nsl; z++) {
        float4 v = src[(size_t)z * nv4 + i];
        s.x += v.x; s.y += v.y; s.z += v.z; s.w += v.w;
    }
    dst[i] = s;
}

// ---------------- causal depthwise conv1d (k=4) + bias + SiLU ----------------
__global__ void conv_silu_kernel(const float* __restrict__ cw,
                                 const float* __restrict__ cb)
{
    int idx = blockIdx.x * blockDim.x + threadIdx.x;
    if (idx >= BL * D4) return;
    int d  = idx & 1023;
    int l  = (idx >> 10) & 1023;
    int bl = idx >> 10;
    float w0 = cw[d * 4], w1 = cw[d * 4 + 1], w2 = cw[d * 4 + 2], w3 = cw[d * 4 + 3];
    const float* xcol = g_xz + d;
    float acc = cb[d];
    if (l >= 3) acc = fmaf(xcol[(size_t)(bl - 3) * 2048], w0, acc);
    if (l >= 2) acc = fmaf(xcol[(size_t)(bl - 2) * 2048], w1, acc);
    if (l >= 1) acc = fmaf(xcol[(size_t)(bl - 1) * 2048], w2, acc);
    acc = fmaf(xcol[(size_t)bl * 2048], w3, acc);
    float s = 1.f / (1.f + __expf(-acc));
    g_xc[idx] = acc * s;
}

// ---------------- delta = softplus(dlow @ dtproj_W + b) ----------------
__global__ void delta_kernel(const float* __restrict__ dtW,
                             const float* __restrict__ dtb)
{
    int idx = blockIdx.x * blockDim.x + threadIdx.x;
    if (idx >= BL * D4) return;
    int n = idx & 1023;
    int m = idx >> 10;
    const float* xr = g_xdbl + (size_t)m * XDBL_N;
    float acc = dtb[n];
    #pragma unroll
    for (int k = 0; k < DTR; k++)
        acc = fmaf(xr[k], dtW[k * 1024 + n], acc);
    g_dlt[idx] = (acc > 20.f) ? acc : log1pf(__expf(acc));
}

// ---------------- selective scan: smem-staged + shfl butterfly ----------------
#define TC 64
__global__ void __launch_bounds__(128) scan_kernel(
    const float* __restrict__ A_log,
    const float* __restrict__ D_skip)
{
    __shared__ float Bsh[TC][64];
    __shared__ float Csh[TC][64];
    __shared__ float dts[4][TC], xcs[4][TC], zsh[4][TC], ysh[4][TC];

    const int b    = blockIdx.y;
    const int d0   = blockIdx.x * 4;
    const int tid  = threadIdx.x;
    const int wi   = tid >> 5;
    const int lane = tid & 31;
    const int d    = d0 + wi;
    const int n0   = lane << 1;

    const float a0 = -__expf(A_log[d * 64 + n0]);
    const float a1 = -__expf(A_log[d * 64 + n0 + 1]);
    const float Dd = D_skip[d];
    float h0 = 0.f, h1 = 0.f;

    const size_t rbase = (size_t)b * 1024;

    for (int c = 0; c < 1024 / TC; c++) {
        const int t0 = c * TC;
        #pragma unroll 4
        for (int i = tid; i < TC * 32; i += 128) {
            int t = i >> 5, q = i & 31;
            const float* xd = g_xdbl + (rbase + t0 + t) * XDBL_N + DTR;
            float2 bvv = *(const float2*)(xd + 2 * q);
            float2 cvv = *(const float2*)(xd + 64 + 2 * q);
            *(float2*)&Bsh[t][2 * q] = bvv;
            *(float2*)&Csh[t][2 * q] = cvv;
        }
        #pragma unroll 2
        for (int i = tid; i < 4 * TC; i += 128) {
            int t = i >> 2, di = i & 3;
            size_t row = rbase + t0 + t;
            dts[di][t] = g_dlt[row * 1024 + d0 + di];
            xcs[di][t] = g_xc [row * 1024 + d0 + di];
            zsh[di][t] = g_xz [row * 2048 + 1024 + d0 + di];
        }
        __syncthreads();

        #pragma unroll 8
        for (int t = 0; t < TC; t++) {
            float dt = dts[wi][t];
            float xv = xcs[wi][t];
            float2 Bv = *(const float2*)&Bsh[t][n0];
            float2 Cv = *(const float2*)&Csh[t][n0];
            float dx = dt * xv;
            h0 = fmaf(__expf(dt * a0), h0, dx * Bv.x);
            h1 = fmaf(__expf(dt * a1), h1, dx * Bv.y);
            float p = fmaf(h0, Cv.x, h1 * Cv.y);
            p += __shfl_xor_sync(0xffffffffu, p, 16);
            p += __shfl_xor_sync(0xffffffffu, p, 8);
            p += __shfl_xor_sync(0xffffffffu, p, 4);
            p += __shfl_xor_sync(0xffffffffu, p, 2);
            p += __shfl_xor_sync(0xffffffffu, p, 1);
            if (lane == 0) {
                float zv = zsh[wi][t];
                float s  = zv / (1.f + __expf(-zv));
                ysh[wi][t] = (p + xv * Dd) * s;
            }
        }
        __syncthreads();

        #pragma unroll 2
        for (int i = tid; i < 4 * TC; i += 128) {
            int t = i >> 2, di = i & 3;
            g_y[(rbase + t0 + t) * 1024 + d0 + di] = ysh[di][t];
        }
        __syncthreads();
    }
}

// ---------------- launcher ----------------
extern "C" void kernel_launch(void* const* d_in, const int* in_sizes, int n_in,
                              void* d_out, int out_size)
{
    const float* q_r   = (const float*)d_in[0];
    const float* q_i   = (const float*)d_in[1];
    const float* q_j   = (const float*)d_in[2];
    const float* q_k   = (const float*)d_in[3];
    const float* inWr  = (const float*)d_in[4];
    const float* inWi  = (const float*)d_in[5];
    const float* inWj  = (const float*)d_in[6];
    const float* inWk  = (const float*)d_in[7];
    const float* convw = (const float*)d_in[8];
    const float* convb = (const float*)d_in[9];
    const float* xprojW= (const float*)d_in[10];
    const float* dtW   = (const float*)d_in[11];
    const float* dtb   = (const float*)d_in[12];
    const float* A_log = (const float*)d_in[13];
    const float* Dskip = (const float*)d_in[14];
    const float* outWr = (const float*)d_in[15];
    const float* outWi = (const float*)d_in[16];
    const float* outWj = (const float*)d_in[17];
    const float* outWk = (const float*)d_in[18];

    float *xz, *xc, *xp, *xdbl, *yb;
    bf16 *winh, *winl, *wouth, *woutl, *xpwh, *xpwl;
    bf16 *ah, *al, *xch, *xcl, *yh, *yl;
    cudaGetSymbolAddress((void**)&xz,    g_xz);
    cudaGetSymbolAddress((void**)&xc,    g_xc);
    cudaGetSymbolAddress((void**)&xp,    g_xp);
    cudaGetSymbolAddress((void**)&xdbl,  g_xdbl);
    cudaGetSymbolAddress((void**)&yb,    g_y);
    cudaGetSymbolAddress((void**)&winh,  g_winh);
    cudaGetSymbolAddress((void**)&winl,  g_winl);
    cudaGetSymbolAddress((void**)&wouth, g_wouth);
    cudaGetSymbolAddress((void**)&woutl, g_woutl);
    cudaGetSymbolAddress((void**)&xpwh,  g_xpwh);
    cudaGetSymbolAddress((void**)&xpwl,  g_xpwl);
    cudaGetSymbolAddress((void**)&ah,    g_ah);
    cudaGetSymbolAddress((void**)&al,    g_al);
    cudaGetSymbolAddress((void**)&xch,   g_xch);
    cudaGetSymbolAddress((void**)&xcl,   g_xcl);
    cudaGetSymbolAddress((void**)&yh,    g_yh);
    cudaGetSymbolAddress((void**)&yl,    g_yl);

    cudaFuncSetAttribute(mma_gemm<false>,
                         cudaFuncAttributeMaxDynamicSharedMemorySize, GSMEM);
    cudaFuncSetAttribute(mma_gemm<true>,
                         cudaFuncAttributeMaxDynamicSharedMemorySize, GSMEM);

    // 0) expand weights (quaternion in/out + xproj transpose), bf16 hi/lo
    {
        int total = 2048 * 512 + 512 * 1024 + XN_PAD * 1024;
        expand_kernel<<<(total + 255) / 256, 256>>>(
            inWr, inWi, inWj, inWk, outWr, outWi, outWj, outWk, xprojW);
    }

    // 1a) split q concat -> bf16 hi/lo A
    qsplit_kernel<<<(BL * 512 / 4 + 255) / 256, 256>>>(q_r, q_i, q_j, q_k);
    // 1b) in_proj: [2048,512] x [512,2048] -> g_xz
    mma_gemm<false><<<dim3(32, 16, 1), 256, GSMEM>>>(
        ah, al, winh, winl, xz, BL, 512, 512, 2048);

    // 2) depthwise conv + bias + SiLU -> g_xc
    conv_silu_kernel<<<(BL * D4) / 256, 256>>>(convw, convb);

    // 3) xproj: split A, then mma split-K=8 -> partials -> g_xdbl
    fsplit_kernel<<<(BL * 1024 / 4 + 255) / 256, 256>>>((const float4*)xc, xch, xcl,
                                                        BL * 1024 / 4);
    mma_gemm<true><<<dim3(3, 16, 8), 256, GSMEM>>>(
        xch, xcl, xpwh, xpwl, xp, BL, 1024, 128, XDBL_N);
    reduce_kernel<<<(BL * XDBL_N / 4 + 255) / 256, 256>>>(
        (const float4*)xp, (float4*)xdbl, BL * XDBL_N / 4, 8);

    // 4) delta = softplus(dlow @ dtW + b) -> g_dlt
    delta_kernel<<<(BL * D4) / 256, 256>>>(dtW, dtb);

    // 5) selective scan + skip + z-gate -> g_y
    scan_kernel<<<dim3(256, BB), 128>>>(A_log, Dskip);

    // 6) out_proj: split A, mma split-K=2 -> partials -> d_out
    fsplit_kernel<<<(BL * 1024 / 4 + 255) / 256, 256>>>((const float4*)yb, yh, yl,
                                                        BL * 1024 / 4);
    mma_gemm<false><<<dim3(8, 16, 2), 256, GSMEM>>>(
        yh, yl, wouth, woutl, xp, BL, 1024, 512, 512);
    reduce_kernel<<<(BL * 512 / 4 + 255) / 256, 256>>>(
        (const float4*)xp, (float4*)d_out, BL * 512 / 4, 2);
}

// round 8
// speedup vs baseline: 2.8528x; 1.0265x over previous
#include <cuda_runtime.h>
#include <cuda_bf16.h>
#include <cstdint>

typedef unsigned long long ull;
typedef __nv_bfloat16 bf16;

// ---------------- problem constants ----------------
#define BB   2
#define LL   1024
#define D4   1024
#define BL   2048            // BB*LL rows
#define DTR  8
#define XDBL_N 136           // DTR + 2*64
#define XN_PAD 192           // padded xproj N for 64-wide tiles

// ---------------- scratch (static device globals; no allocs) ----------------
__device__ float g_xz  [(size_t)BL * 2048];
__device__ float g_xc  [(size_t)BL * D4];
__device__ float g_xdbl[(size_t)BL * XDBL_N];
__device__ float g_xp  [(size_t)8 * BL * XDBL_N];   // split-K partials (xproj)
// bf16-split transposed weights ([N][K], K-major)
__device__ bf16 g_winh [(size_t)2048 * 512],  g_winl [(size_t)2048 * 512];
__device__ bf16 g_wouth[(size_t)512 * 1024],  g_woutl[(size_t)512 * 1024];
__device__ bf16 g_xpwh [(size_t)XN_PAD * 1024], g_xpwl[(size_t)XN_PAD * 1024];
// bf16-split activations
__device__ bf16 g_ah [(size_t)BL * 512],  g_al [(size_t)BL * 512];
__device__ bf16 g_xch[(size_t)BL * 1024], g_xcl[(size_t)BL * 1024];
__device__ bf16 g_yh [(size_t)BL * 1024], g_yl [(size_t)BL * 1024];

// quaternion Hamilton tables
__constant__ int   c_qidx[4][4] = {{0,1,2,3},{1,0,3,2},{2,3,0,1},{3,2,1,0}};
__constant__ float c_qsgn[4][4] = {{ 1.f,-1.f,-1.f,-1.f},
                                   { 1.f, 1.f, 1.f,-1.f},
                                   { 1.f,-1.f, 1.f, 1.f},
                                   { 1.f, 1.f,-1.f, 1.f}};

// ---------------- ptx helpers (sm_80-era, sm_103-legal) ----------------
__device__ __forceinline__ uint32_t smem_u32(const void* p) {
    uint32_t a;
    asm("{ .reg .u64 t; cvta.to.shared.u64 t, %1; cvt.u32.u64 %0, t; }" : "=r"(a) : "l"(p));
    return a;
}
__device__ __forceinline__ void cpa16(uint32_t s, const void* g) {
    asm volatile("cp.async.cg.shared.global [%0], [%1], 16;" :: "r"(s), "l"(g));
}
#define CP_COMMIT() asm volatile("cp.async.commit_group;" ::: "memory")
#define CP_WAIT1()  asm volatile("cp.async.wait_group 1;"  ::: "memory")
#define CP_WAIT0()  asm volatile("cp.async.wait_group 0;"  ::: "memory")
#define LDSM4(R, a) \
    asm volatile("ldmatrix.sync.aligned.m8n8.x4.shared.b16 {%0,%1,%2,%3}, [%4];" \
        : "=r"((R)[0]), "=r"((R)[1]), "=r"((R)[2]), "=r"((R)[3]) : "r"(a))

__device__ __forceinline__ void mma16816(float* d, const uint32_t* a, const uint32_t* b) {
    asm volatile(
        "mma.sync.aligned.m16n8k16.row.col.f32.bf16.bf16.f32 "
        "{%0,%1,%2,%3}, {%4,%5,%6,%7}, {%8,%9}, {%0,%1,%2,%3};"
        : "+f"(d[0]), "+f"(d[1]), "+f"(d[2]), "+f"(d[3])
        : "r"(a[0]), "r"(a[1]), "r"(a[2]), "r"(a[3]), "r"(b[0]), "r"(b[1]));
}

__device__ __forceinline__ void split4(float4 v, uint2& ho, uint2& lo) {
    bf16 hx = __float2bfloat16(v.x), hy = __float2bfloat16(v.y);
    bf16 hz = __float2bfloat16(v.z), hw = __float2bfloat16(v.w);
    __nv_bfloat162 h01 = __halves2bfloat162(hx, hy);
    __nv_bfloat162 h23 = __halves2bfloat162(hz, hw);
    __nv_bfloat162 l01 = __floats2bfloat162_rn(v.x - __bfloat162float(hx),
                                               v.y - __bfloat162float(hy));
    __nv_bfloat162 l23 = __floats2bfloat162_rn(v.z - __bfloat162float(hz),
                                               v.w - __bfloat162float(hw));
    ho = make_uint2(*(uint32_t*)&h01, *(uint32_t*)&h23);
    lo = make_uint2(*(uint32_t*)&l01, *(uint32_t*)&l23);
}

// ---------------- dummy (launch-position shim so ncu captures in_proj) ------
__global__ void dummy_kernel() { if (threadIdx.x == 0) g_xp[0] = 0.f; }

// ---------------- weight expansion ----------------
__global__ void expand_kernel(
    const float* __restrict__ iWr, const float* __restrict__ iWi,
    const float* __restrict__ iWj, const float* __restrict__ iWk,
    const float* __restrict__ oWr, const float* __restrict__ oWi,
    const float* __restrict__ oWj, const float* __restrict__ oWk,
    const float* __restrict__ xpW)
{
    int idx = blockIdx.x * blockDim.x + threadIdx.x;
    const int NIN = 2048 * 512;
    const int NOUT = 512 * 1024;
    float val;
    if (idx < NIN) {
        int n = idx >> 9, k = idx & 511;
        int g = n >> 9, h = k >> 7;
        int wi = c_qidx[g][h];
        const float* W = (wi == 0) ? iWr : (wi == 1) ? iWi : (wi == 2) ? iWj : iWk;
        val = c_qsgn[g][h] * W[(size_t)(k & 127) * 512 + (n & 511)];
        bf16 hi = __float2bfloat16(val);
        g_winh[idx] = hi;
        g_winl[idx] = __float2bfloat16(val - __bfloat162float(hi));
    } else if (idx < NIN + NOUT) {
        int j = idx - NIN;
        int n = j >> 10, k = j & 1023;
        int g = n >> 7, h = k >> 8;
        int wi = c_qidx[g][h];
        const float* W = (wi == 0) ? oWr : (wi == 1) ? oWi : (wi == 2) ? oWj : oWk;
        val = c_qsgn[g][h] * W[(size_t)(k & 255) * 128 + (n & 127)];
        bf16 hi = __float2bfloat16(val);
        g_wouth[j] = hi;
        g_woutl[j] = __float2bfloat16(val - __bfloat162float(hi));
    } else {
        int j = idx - NIN - NOUT;
        if (j >= XN_PAD * 1024) return;
        int n = j >> 10, k = j & 1023;
        val = (n < XDBL_N) ? xpW[(size_t)k * XDBL_N + n] : 0.f;
        bf16 hi = __float2bfloat16(val);
        g_xpwh[j] = hi;
        g_xpwl[j] = __float2bfloat16(val - __bfloat162float(hi));
    }
}

// ---------------- q concat -> bf16 hi/lo ----------------
__global__ void qsplit_kernel(const float* __restrict__ Q0, const float* __restrict__ Q1,
                              const float* __restrict__ Q2, const float* __restrict__ Q3)
{
    int i = blockIdx.x * blockDim.x + threadIdx.x;
    if (i >= BL * 512 / 4) return;
    int m = i >> 7, c4 = i & 127;
    int k = c4 * 4;
    const float* q = (k < 128) ? Q0 : (k < 256) ? Q1 : (k < 384) ? Q2 : Q3;
    float4 v = *(const float4*)(q + (size_t)m * 128 + (k & 127));
    uint2 h, l; split4(v, h, l);
    ((uint2*)g_ah)[i] = h;
    ((uint2*)g_al)[i] = l;
}

// ---------------- mma GEMM: bf16-split, cp.async 2-stage, ldmatrix ----------------
#define GSTG 49152
#define GSMEM (2 * GSTG)
template<bool MASKN>
__global__ void __launch_bounds__(256, 2) mma_gemm(
    const bf16* __restrict__ Ah_g, const bf16* __restrict__ Al_g,
    const bf16* __restrict__ Bh_g, const bf16* __restrict__ Bl_g,
    float* __restrict__ C, int M, int K, int Kc, int Nout)
{
    extern __shared__ char smx[];
    const uint32_t sb = smem_u32(smx);
    const int OFF_AL = 16384, OFF_BH = 32768, OFF_BL = 40960;

    const int tid  = threadIdx.x;
    const int wid  = tid >> 5;
    const int lane = tid & 31;
    const int wm   = wid & 3;
    const int wn   = wid >> 2;
    const int bn0  = blockIdx.x * 64;
    const int bm0  = blockIdx.y * 128;
    const int kb0  = blockIdx.z * Kc;
    const int m_base = wm * 32;
    const int n_base = wn * 32;

    float acc[2][4][4];
    #pragma unroll
    for (int i = 0; i < 2; i++)
        #pragma unroll
        for (int j = 0; j < 4; j++)
            #pragma unroll
            for (int q = 0; q < 4; q++) acc[i][j][q] = 0.f;

    auto issue = [&](int s, int kb) {
        uint32_t st = sb + (s & 1) * GSTG;
        #pragma unroll
        for (int it = 0; it < 4; it++) {
            int c = tid + it * 256;
            int r = c >> 3, ch = c & 7;
            uint32_t so = st + r * 128 + ((ch ^ (r & 7)) << 4);
            const size_t go = (size_t)(bm0 + r) * K + kb + ch * 8;
            cpa16(so,          Ah_g + go);
            cpa16(so + OFF_AL, Al_g + go);
        }
        #pragma unroll
        for (int it = 0; it < 2; it++) {
            int c = tid + it * 256;
            int r = c >> 3, ch = c & 7;
            uint32_t so = st + OFF_BH + r * 128 + ((ch ^ (r & 7)) << 4);
            const size_t go = (size_t)(bn0 + r) * K + kb + ch * 8;
            cpa16(so,                     Bh_g + go);
            cpa16(so + (OFF_BL - OFF_BH), Bl_g + go);
        }
        CP_COMMIT();
    };

    const int ntiles = Kc >> 6;
    issue(0, kb0);

    for (int s = 0; s < ntiles; s++) {
        if (s + 1 < ntiles) { issue(s + 1, kb0 + (s + 1) * 64); CP_WAIT1(); }
        else                { CP_WAIT0(); }
        __syncthreads();
        uint32_t st = sb + (s & 1) * GSTG;

        #pragma unroll
        for (int kk = 0; kk < 64; kk += 16) {
            uint32_t ah[2][4], al[2][4];
            #pragma unroll
            for (int mi = 0; mi < 2; mi++) {
                int m  = m_base + mi * 16 + (lane & 15);
                int kc = (kk >> 3) + (lane >> 4);
                uint32_t ad = st + m * 128 + (((kc) ^ (m & 7)) << 4);
                LDSM4(ah[mi], ad);
                LDSM4(al[mi], ad + OFF_AL);
            }
            uint32_t bh[4][2], bl[4][2];
            #pragma unroll
            for (int nj = 0; nj < 2; nj++) {
                int n  = n_base + nj * 16 + (lane & 7) + ((lane >> 4) << 3);
                int kc = (kk >> 3) + ((lane >> 3) & 1);
                uint32_t bd = st + OFF_BH + n * 128 + (((kc) ^ (n & 7)) << 4);
                uint32_t rh[4], rl[4];
                LDSM4(rh, bd);
                LDSM4(rl, bd + (OFF_BL - OFF_BH));
                bh[2*nj][0] = rh[0]; bh[2*nj][1] = rh[1];
                bh[2*nj+1][0] = rh[2]; bh[2*nj+1][1] = rh[3];
                bl[2*nj][0] = rl[0]; bl[2*nj][1] = rl[1];
                bl[2*nj+1][0] = rl[2]; bl[2*nj+1][1] = rl[3];
            }
            #pragma unroll
            for (int mi = 0; mi < 2; mi++)
                #pragma unroll
                for (int ni = 0; ni < 4; ni++) {
                    mma16816(acc[mi][ni], ah[mi], bh[ni]);
                    mma16816(acc[mi][ni], ah[mi], bl[ni]);
                    mma16816(acc[mi][ni], al[mi], bh[ni]);
                }
        }
        __syncthreads();
    }

    float* Cz = C + (size_t)blockIdx.z * M * Nout;
    #pragma unroll
    for (int mi = 0; mi < 2; mi++) {
        #pragma unroll
        for (int ni = 0; ni < 4; ni++) {
            int r = bm0 + m_base + mi * 16 + (lane >> 2);
            int c = bn0 + n_base + ni * 8 + (lane & 3) * 2;
            if (MASKN && c >= Nout) continue;
            *(float2*)&Cz[(size_t)r * Nout + c] =
                make_float2(acc[mi][ni][0], acc[mi][ni][1]);
            *(float2*)&Cz[(size_t)(r + 8) * Nout + c] =
                make_float2(acc[mi][ni][2], acc[mi][ni][3]);
        }
    }
}

// ---------------- split-K reduction (xproj) ----------------
__global__ void reduce_kernel(const float4* __restrict__ src, float4* __restrict__ dst,
                              int nv4, int nsl)
{
    int i = blockIdx.x * blockDim.x + threadIdx.x;
    if (i >= nv4) return;
    float4 s = src[i];
    for (int z = 1; z < nsl; z++) {
        float4 v = src[(size_t)z * nv4 + i];
        s.x += v.x; s.y += v.y; s.z += v.z; s.w += v.w;
    }
    dst[i] = s;
}

// ---------------- conv1d + bias + SiLU, fused bf16 hi/lo split ----------------
__global__ void conv_silu_kernel(const float* __restrict__ cw,
                                 const float* __restrict__ cb)
{
    int idx = blockIdx.x * blockDim.x + threadIdx.x;   // over BL*512, 2 chans each
    if (idx >= BL * 512) return;
    int d2 = idx & 511;
    int bl = idx >> 9;
    int d  = d2 * 2;
    int l  = bl & 1023;
    float4 w0 = *(const float4*)(cw + d * 4);
    float4 w1 = *(const float4*)(cw + d * 4 + 4);
    float2 bias = *(const float2*)(cb + d);
    const float* xcol = g_xz + d;
    float a0 = bias.x, a1 = bias.y;
    if (l >= 3) { float2 v = *(const float2*)(xcol + (size_t)(bl - 3) * 2048);
                  a0 = fmaf(v.x, w0.x, a0); a1 = fmaf(v.y, w1.x, a1); }
    if (l >= 2) { float2 v = *(const float2*)(xcol + (size_t)(bl - 2) * 2048);
                  a0 = fmaf(v.x, w0.y, a0); a1 = fmaf(v.y, w1.y, a1); }
    if (l >= 1) { float2 v = *(const float2*)(xcol + (size_t)(bl - 1) * 2048);
                  a0 = fmaf(v.x, w0.z, a0); a1 = fmaf(v.y, w1.z, a1); }
    { float2 v = *(const float2*)(xcol + (size_t)bl * 2048);
      a0 = fmaf(v.x, w0.w, a0); a1 = fmaf(v.y, w1.w, a1); }
    float y0 = a0 / (1.f + __expf(-a0));
    float y1 = a1 / (1.f + __expf(-a1));
    size_t o = (size_t)bl * 1024 + d;
    *(float2*)(g_xc + o) = make_float2(y0, y1);
    bf16 h0 = __float2bfloat16(y0), h1 = __float2bfloat16(y1);
    __nv_bfloat162 hp = __halves2bfloat162(h0, h1);
    __nv_bfloat162 lp = __floats2bfloat162_rn(y0 - __bfloat162float(h0),
                                              y1 - __bfloat162float(h1));
    *(uint32_t*)(g_xch + o) = *(uint32_t*)&hp;
    *(uint32_t*)(g_xcl + o) = *(uint32_t*)&lp;
}

// ---------------- selective scan: fused delta, bf16-split y output ----------------
#define TC 64
__global__ void __launch_bounds__(128) scan_kernel(
    const float* __restrict__ A_log,
    const float* __restrict__ D_skip,
    const float* __restrict__ dtW,
    const float* __restrict__ dtb)
{
    __shared__ float Bsh[TC][64];
    __shared__ float Csh[TC][64];
    __shared__ float dts[4][TC], xcs[4][TC], zsh[4][TC], ysh[4][TC];
    __shared__ float wts[4][8], dtb_s[4];

    const int b    = blockIdx.y;
    const int d0   = blockIdx.x * 4;
    const int tid  = threadIdx.x;
    const int wi   = tid >> 5;
    const int lane = tid & 31;
    const int d    = d0 + wi;
    const int n0   = lane << 1;

    if (tid < 32) wts[tid >> 3][tid & 7] = dtW[(tid & 7) * 1024 + d0 + (tid >> 3)];
    if (tid < 4)  dtb_s[tid] = dtb[d0 + tid];

    const float a0 = -__expf(A_log[d * 64 + n0]);
    const float a1 = -__expf(A_log[d * 64 + n0 + 1]);
    const float Dd = D_skip[d];
    float h0 = 0.f, h1 = 0.f;

    const size_t rbase = (size_t)b * 1024;
    __syncthreads();

    for (int c = 0; c < 1024 / TC; c++) {
        const int t0 = c * TC;
        #pragma unroll 4
        for (int i = tid; i < TC * 32; i += 128) {
            int t = i >> 5, q = i & 31;
            const float* xd = g_xdbl + (rbase + t0 + t) * XDBL_N + DTR;
            float2 bvv = *(const float2*)(xd + 2 * q);
            float2 cvv = *(const float2*)(xd + 64 + 2 * q);
            *(float2*)&Bsh[t][2 * q] = bvv;
            *(float2*)&Csh[t][2 * q] = cvv;
        }
        #pragma unroll 2
        for (int i = tid; i < 4 * TC; i += 128) {
            int t = i >> 2, di = i & 3;
            size_t row = rbase + t0 + t;
            const float* xd = g_xdbl + row * XDBL_N;
            float acc = dtb_s[di];
            #pragma unroll
            for (int k = 0; k < DTR; k++)
                acc = fmaf(xd[k], wts[di][k], acc);
            dts[di][t] = (acc > 20.f) ? acc : log1pf(__expf(acc));
            xcs[di][t] = g_xc[row * 1024 + d0 + di];
            zsh[di][t] = g_xz[row * 2048 + 1024 + d0 + di];
        }
        __syncthreads();

        #pragma unroll 8
        for (int t = 0; t < TC; t++) {
            float dt = dts[wi][t];
            float xv = xcs[wi][t];
            float2 Bv = *(const float2*)&Bsh[t][n0];
            float2 Cv = *(const float2*)&Csh[t][n0];
            float dx = dt * xv;
            h0 = fmaf(__expf(dt * a0), h0, dx * Bv.x);
            h1 = fmaf(__expf(dt * a1), h1, dx * Bv.y);
            float p = fmaf(h0, Cv.x, h1 * Cv.y);
            p += __shfl_xor_sync(0xffffffffu, p, 16);
            p += __shfl_xor_sync(0xffffffffu, p, 8);
            p += __shfl_xor_sync(0xffffffffu, p, 4);
            p += __shfl_xor_sync(0xffffffffu, p, 2);
            p += __shfl_xor_sync(0xffffffffu, p, 1);
            if (lane == 0) {
                float zv = zsh[wi][t];
                float s  = zv / (1.f + __expf(-zv));
                ysh[wi][t] = (p + xv * Dd) * s;
            }
        }
        __syncthreads();

        #pragma unroll 2
        for (int i = tid; i < 4 * TC; i += 128) {
            int t = i >> 2, di = i & 3;
            float v = ysh[di][t];
            bf16 hv = __float2bfloat16(v);
            size_t o = (rbase + t0 + t) * 1024 + d0 + di;
            g_yh[o] = hv;
            g_yl[o] = __float2bfloat16(v - __bfloat162float(hv));
        }
        __syncthreads();
    }
}

// ---------------- launcher ----------------
extern "C" void kernel_launch(void* const* d_in, const int* in_sizes, int n_in,
                              void* d_out, int out_size)
{
    const float* q_r   = (const float*)d_in[0];
    const float* q_i   = (const float*)d_in[1];
    const float* q_j   = (const float*)d_in[2];
    const float* q_k   = (const float*)d_in[3];
    const float* inWr  = (const float*)d_in[4];
    const float* inWi  = (const float*)d_in[5];
    const float* inWj  = (const float*)d_in[6];
    const float* inWk  = (const float*)d_in[7];
    const float* convw = (const float*)d_in[8];
    const float* convb = (const float*)d_in[9];
    const float* xprojW= (const float*)d_in[10];
    const float* dtW   = (const float*)d_in[11];
    const float* dtb   = (const float*)d_in[12];
    const float* A_log = (const float*)d_in[13];
    const float* Dskip = (const float*)d_in[14];
    const float* outWr = (const float*)d_in[15];
    const float* outWi = (const float*)d_in[16];
    const float* outWj = (const float*)d_in[17];
    const float* outWk = (const float*)d_in[18];

    float *xz, *xp, *xdbl;
    bf16 *winh, *winl, *wouth, *woutl, *xpwh, *xpwl, *ah, *al, *xch, *xcl, *yh, *yl;
    cudaGetSymbolAddress((void**)&xz,    g_xz);
    cudaGetSymbolAddress((void**)&xp,    g_xp);
    cudaGetSymbolAddress((void**)&xdbl,  g_xdbl);
    cudaGetSymbolAddress((void**)&winh,  g_winh);
    cudaGetSymbolAddress((void**)&winl,  g_winl);
    cudaGetSymbolAddress((void**)&wouth, g_wouth);
    cudaGetSymbolAddress((void**)&woutl, g_woutl);
    cudaGetSymbolAddress((void**)&xpwh,  g_xpwh);
    cudaGetSymbolAddress((void**)&xpwl,  g_xpwl);
    cudaGetSymbolAddress((void**)&ah,    g_ah);
    cudaGetSymbolAddress((void**)&al,    g_al);
    cudaGetSymbolAddress((void**)&xch,   g_xch);
    cudaGetSymbolAddress((void**)&xcl,   g_xcl);
    cudaGetSymbolAddress((void**)&yh,    g_yh);
    cudaGetSymbolAddress((void**)&yl,    g_yl);

    cudaFuncSetAttribute(mma_gemm<false>,
                         cudaFuncAttributeMaxDynamicSharedMemorySize, GSMEM);
    cudaFuncSetAttribute(mma_gemm<true>,
                         cudaFuncAttributeMaxDynamicSharedMemorySize, GSMEM);

    // 1) expand weights
    {
        int total = 2048 * 512 + 512 * 1024 + XN_PAD * 1024;
        expand_kernel<<<(total + 255) / 256, 256>>>(
            inWr, inWi, inWj, inWk, outWr, outWi, outWj, outWk, xprojW);
    }
    // 2) split q -> bf16 hi/lo
    qsplit_kernel<<<(BL * 512 / 4 + 255) / 256, 256>>>(q_r, q_i, q_j, q_k);
    // 3) dummy (ncu launch-position shim: next launch is captured)
    dummy_kernel<<<1, 32>>>();
    // 4) in_proj: [2048,512] x [512,2048] -> g_xz     <-- profiled launch
    mma_gemm<false><<<dim3(32, 16, 1), 256, GSMEM>>>(
        ah, al, winh, winl, xz, BL, 512, 512, 2048);
    // 5) conv + SiLU + bf16 split -> g_xc, g_xch/l
    conv_silu_kernel<<<(BL * 512 + 255) / 256, 256>>>(convw, convb);
    // 6) xproj split-K=8 -> partials
    mma_gemm<true><<<dim3(3, 16, 8), 256, GSMEM>>>(
        xch, xcl, xpwh, xpwl, xp, BL, 1024, 128, XDBL_N);
    // 7) reduce -> g_xdbl
    reduce_kernel<<<(BL * XDBL_N / 4 + 255) / 256, 256>>>(
        (const float4*)xp, (float4*)xdbl, BL * XDBL_N / 4, 8);
    // 8) scan (fused delta + gate + bf16 split) -> g_yh/l
    scan_kernel<<<dim3(256, BB), 128>>>(A_log, Dskip, dtW, dtb);
    // 9) out_proj: [2048,1024] x [1024,512] -> d_out (no split-K)
    mma_gemm<false><<<dim3(8, 16, 1), 256, GSMEM>>>(
        yh, yl, wouth, woutl, (float*)d_out, BL, 1024, 1024, 512);
}

// round 9
// speedup vs baseline: 5.0408x; 1.7670x over previous
#include <cuda_runtime.h>
#include <cuda_bf16.h>
#include <cstdint>

typedef unsigned long long ull;
typedef __nv_bfloat16 bf16;

// ---------------- problem constants ----------------
#define BB   2
#define LL   1024
#define D4   1024
#define BL   2048            // BB*LL rows
#define DTR  8
#define XDBL_N 136           // DTR + 2*64
#define XN_PAD 192           // padded xproj N for 64-wide tiles

// ---------------- scratch (static device globals; no allocs) ----------------
__device__ float g_xz  [(size_t)BL * 2048];
__device__ float g_xc  [(size_t)BL * D4];
__device__ float g_xdbl[(size_t)BL * XDBL_N];
__device__ float g_xp  [(size_t)8 * BL * XDBL_N];   // split-K partials (shared scratch)
// bf16-split transposed weights ([N][K], K-major)
__device__ bf16 g_winh [(size_t)2048 * 512],  g_winl [(size_t)2048 * 512];
__device__ bf16 g_wouth[(size_t)512 * 1024],  g_woutl[(size_t)512 * 1024];
__device__ bf16 g_xpwh [(size_t)XN_PAD * 1024], g_xpwl[(size_t)XN_PAD * 1024];
// bf16-split activations
__device__ bf16 g_ah [(size_t)BL * 512],  g_al [(size_t)BL * 512];
__device__ bf16 g_xch[(size_t)BL * 1024], g_xcl[(size_t)BL * 1024];
__device__ bf16 g_yh [(size_t)BL * 1024], g_yl [(size_t)BL * 1024];

// quaternion Hamilton tables
__constant__ int   c_qidx[4][4] = {{0,1,2,3},{1,0,3,2},{2,3,0,1},{3,2,1,0}};
__constant__ float c_qsgn[4][4] = {{ 1.f,-1.f,-1.f,-1.f},
                                   { 1.f, 1.f, 1.f,-1.f},
                                   { 1.f,-1.f, 1.f, 1.f},
                                   { 1.f, 1.f,-1.f, 1.f}};

// ---------------- ptx helpers (sm_80-era, sm_103-legal) ----------------
__device__ __forceinline__ uint32_t smem_u32(const void* p) {
    uint32_t a;
    asm("{ .reg .u64 t; cvta.to.shared.u64 t, %1; cvt.u32.u64 %0, t; }" : "=r"(a) : "l"(p));
    return a;
}
__device__ __forceinline__ void cpa16(uint32_t s, const void* g) {
    asm volatile("cp.async.cg.shared.global [%0], [%1], 16;" :: "r"(s), "l"(g));
}
#define CP_COMMIT() asm volatile("cp.async.commit_group;" ::: "memory")
#define CP_WAIT1()  asm volatile("cp.async.wait_group 1;"  ::: "memory")
#define CP_WAIT0()  asm volatile("cp.async.wait_group 0;"  ::: "memory")
#define LDSM4(R, a) \
    asm volatile("ldmatrix.sync.aligned.m8n8.x4.shared.b16 {%0,%1,%2,%3}, [%4];" \
        : "=r"((R)[0]), "=r"((R)[1]), "=r"((R)[2]), "=r"((R)[3]) : "r"(a))

__device__ __forceinline__ void mma16816(float* d, const uint32_t* a, const uint32_t* b) {
    asm volatile(
        "mma.sync.aligned.m16n8k16.row.col.f32.bf16.bf16.f32 "
        "{%0,%1,%2,%3}, {%4,%5,%6,%7}, {%8,%9}, {%0,%1,%2,%3};"
        : "+f"(d[0]), "+f"(d[1]), "+f"(d[2]), "+f"(d[3])
        : "r"(a[0]), "r"(a[1]), "r"(a[2]), "r"(a[3]), "r"(b[0]), "r"(b[1]));
}

__device__ __forceinline__ void split4(float4 v, uint2& ho, uint2& lo) {
    bf16 hx = __float2bfloat16(v.x), hy = __float2bfloat16(v.y);
    bf16 hz = __float2bfloat16(v.z), hw = __float2bfloat16(v.w);
    __nv_bfloat162 h01 = __halves2bfloat162(hx, hy);
    __nv_bfloat162 h23 = __halves2bfloat162(hz, hw);
    __nv_bfloat162 l01 = __floats2bfloat162_rn(v.x - __bfloat162float(hx),
                                               v.y - __bfloat162float(hy));
    __nv_bfloat162 l23 = __floats2bfloat162_rn(v.z - __bfloat162float(hz),
                                               v.w - __bfloat162float(hw));
    ho = make_uint2(*(uint32_t*)&h01, *(uint32_t*)&h23);
    lo = make_uint2(*(uint32_t*)&l01, *(uint32_t*)&l23);
}

// ---------------- weight expansion + q-split (single prologue kernel) --------
__global__ void expand_kernel(
    const float* __restrict__ iWr, const float* __restrict__ iWi,
    const float* __restrict__ iWj, const float* __restrict__ iWk,
    const float* __restrict__ oWr, const float* __restrict__ oWi,
    const float* __restrict__ oWj, const float* __restrict__ oWk,
    const float* __restrict__ xpW,
    const float* __restrict__ Q0, const float* __restrict__ Q1,
    const float* __restrict__ Q2, const float* __restrict__ Q3)
{
    int idx = blockIdx.x * blockDim.x + threadIdx.x;
    const int NIN = 2048 * 512;
    const int NOUT = 512 * 1024;
    const int NXP = XN_PAD * 1024;
    float val;
    if (idx < NIN) {
        int n = idx >> 9, k = idx & 511;
        int g = n >> 9, h = k >> 7;
        int wi = c_qidx[g][h];
        const float* W = (wi == 0) ? iWr : (wi == 1) ? iWi : (wi == 2) ? iWj : iWk;
        val = c_qsgn[g][h] * W[(size_t)(k & 127) * 512 + (n & 511)];
        bf16 hi = __float2bfloat16(val);
        g_winh[idx] = hi;
        g_winl[idx] = __float2bfloat16(val - __bfloat162float(hi));
    } else if (idx < NIN + NOUT) {
        int j = idx - NIN;
        int n = j >> 10, k = j & 1023;
        int g = n >> 7, h = k >> 8;
        int wi = c_qidx[g][h];
        const float* W = (wi == 0) ? oWr : (wi == 1) ? oWi : (wi == 2) ? oWj : oWk;
        val = c_qsgn[g][h] * W[(size_t)(k & 255) * 128 + (n & 127)];
        bf16 hi = __float2bfloat16(val);
        g_wouth[j] = hi;
        g_woutl[j] = __float2bfloat16(val - __bfloat162float(hi));
    } else if (idx < NIN + NOUT + NXP) {
        int j = idx - NIN - NOUT;
        int n = j >> 10, k = j & 1023;
        val = (n < XDBL_N) ? xpW[(size_t)k * XDBL_N + n] : 0.f;
        bf16 hi = __float2bfloat16(val);
        g_xpwh[j] = hi;
        g_xpwl[j] = __float2bfloat16(val - __bfloat162float(hi));
    } else {
        int j = idx - NIN - NOUT - NXP;              // q-split: float4 items
        if (j >= BL * 128) return;
        int m = j >> 7, c4 = j & 127;
        int k = c4 * 4;
        const float* q = (k < 128) ? Q0 : (k < 256) ? Q1 : (k < 384) ? Q2 : Q3;
        float4 v = *(const float4*)(q + (size_t)m * 128 + (k & 127));
        uint2 h, l; split4(v, h, l);
        ((uint2*)g_ah)[j] = h;
        ((uint2*)g_al)[j] = l;
    }
}

// ---------------- mma GEMM: bf16-split, cp.async 2-stage, ldmatrix ----------------
#define GSTG 49152
#define GSMEM (2 * GSTG)
template<bool MASKN>
__global__ void __launch_bounds__(256, 2) mma_gemm(
    const bf16* __restrict__ Ah_g, const bf16* __restrict__ Al_g,
    const bf16* __restrict__ Bh_g, const bf16* __restrict__ Bl_g,
    float* __restrict__ C, int M, int K, int Kc, int Nout)
{
    extern __shared__ char smx[];
    const uint32_t sb = smem_u32(smx);
    const int OFF_AL = 16384, OFF_BH = 32768, OFF_BL = 40960;

    const int tid  = threadIdx.x;
    const int wid  = tid >> 5;
    const int lane = tid & 31;
    const int wm   = wid & 3;
    const int wn   = wid >> 2;
    const int bn0  = blockIdx.x * 64;
    const int bm0  = blockIdx.y * 128;
    const int kb0  = blockIdx.z * Kc;
    const int m_base = wm * 32;
    const int n_base = wn * 32;

    float acc[2][4][4];
    #pragma unroll
    for (int i = 0; i < 2; i++)
        #pragma unroll
        for (int j = 0; j < 4; j++)
            #pragma unroll
            for (int q = 0; q < 4; q++) acc[i][j][q] = 0.f;

    auto issue = [&](int s, int kb) {
        uint32_t st = sb + (s & 1) * GSTG;
        #pragma unroll
        for (int it = 0; it < 4; it++) {
            int c = tid + it * 256;
            int r = c >> 3, ch = c & 7;
            uint32_t so = st + r * 128 + ((ch ^ (r & 7)) << 4);
            const size_t go = (size_t)(bm0 + r) * K + kb + ch * 8;
            cpa16(so,          Ah_g + go);
            cpa16(so + OFF_AL, Al_g + go);
        }
        #pragma unroll
        for (int it = 0; it < 2; it++) {
            int c = tid + it * 256;
            int r = c >> 3, ch = c & 7;
            uint32_t so = st + OFF_BH + r * 128 + ((ch ^ (r & 7)) << 4);
            const size_t go = (size_t)(bn0 + r) * K + kb + ch * 8;
            cpa16(so,                     Bh_g + go);
            cpa16(so + (OFF_BL - OFF_BH), Bl_g + go);
        }
        CP_COMMIT();
    };

    const int ntiles = Kc >> 6;
    issue(0, kb0);

    for (int s = 0; s < ntiles; s++) {
        if (s + 1 < ntiles) { issue(s + 1, kb0 + (s + 1) * 64); CP_WAIT1(); }
        else                { CP_WAIT0(); }
        __syncthreads();
        uint32_t st = sb + (s & 1) * GSTG;

        #pragma unroll
        for (int kk = 0; kk < 64; kk += 16) {
            uint32_t ah[2][4], al[2][4];
            #pragma unroll
            for (int mi = 0; mi < 2; mi++) {
                int m  = m_base + mi * 16 + (lane & 15);
                int kc = (kk >> 3) + (lane >> 4);
                uint32_t ad = st + m * 128 + (((kc) ^ (m & 7)) << 4);
                LDSM4(ah[mi], ad);
                LDSM4(al[mi], ad + OFF_AL);
            }
            uint32_t bh[4][2], bl[4][2];
            #pragma unroll
            for (int nj = 0; nj < 2; nj++) {
                int n  = n_base + nj * 16 + (lane & 7) + ((lane >> 4) << 3);
                int kc = (kk >> 3) + ((lane >> 3) & 1);
                uint32_t bd = st + OFF_BH + n * 128 + (((kc) ^ (n & 7)) << 4);
                uint32_t rh[4], rl[4];
                LDSM4(rh, bd);
                LDSM4(rl, bd + (OFF_BL - OFF_BH));
                bh[2*nj][0] = rh[0]; bh[2*nj][1] = rh[1];
                bh[2*nj+1][0] = rh[2]; bh[2*nj+1][1] = rh[3];
                bl[2*nj][0] = rl[0]; bl[2*nj][1] = rl[1];
                bl[2*nj+1][0] = rl[2]; bl[2*nj+1][1] = rl[3];
            }
            #pragma unroll
            for (int mi = 0; mi < 2; mi++)
                #pragma unroll
                for (int ni = 0; ni < 4; ni++) {
                    mma16816(acc[mi][ni], ah[mi], bh[ni]);
                    mma16816(acc[mi][ni], ah[mi], bl[ni]);
                    mma16816(acc[mi][ni], al[mi], bh[ni]);
                }
        }
        __syncthreads();
    }

    float* Cz = C + (size_t)blockIdx.z * M * Nout;
    #pragma unroll
    for (int mi = 0; mi < 2; mi++) {
        #pragma unroll
        for (int ni = 0; ni < 4; ni++) {
            int r = bm0 + m_base + mi * 16 + (lane >> 2);
            int c = bn0 + n_base + ni * 8 + (lane & 3) * 2;
            if (MASKN && c >= Nout) continue;
            *(float2*)&Cz[(size_t)r * Nout + c] =
                make_float2(acc[mi][ni][0], acc[mi][ni][1]);
            *(float2*)&Cz[(size_t)(r + 8) * Nout + c] =
                make_float2(acc[mi][ni][2], acc[mi][ni][3]);
        }
    }
}

// ---------------- split-K reduction ----------------
__global__ void reduce_kernel(const float4* __restrict__ src, float4* __restrict__ dst,
                              int nv4, int nsl)
{
    int i = blockIdx.x * blockDim.x + threadIdx.x;
    if (i >= nv4) return;
    float4 s = src[i];
    for (int z = 1; z < nsl; z++) {
        float4 v = src[(size_t)z * nv4 + i];
        s.x += v.x; s.y += v.y; s.z += v.z; s.w += v.w;
    }
    dst[i] = s;
}

// ---------------- conv1d + bias + SiLU, fused bf16 hi/lo split ----------------
__global__ void conv_silu_kernel(const float* __restrict__ cw,
                                 const float* __restrict__ cb)
{
    int idx = blockIdx.x * blockDim.x + threadIdx.x;
    if (idx >= BL * 512) return;
    int d2 = idx & 511;
    int bl = idx >> 9;
    int d  = d2 * 2;
    int l  = bl & 1023;
    float4 w0 = *(const float4*)(cw + d * 4);
    float4 w1 = *(const float4*)(cw + d * 4 + 4);
    float2 bias = *(const float2*)(cb + d);
    const float* xcol = g_xz + d;
    float a0 = bias.x, a1 = bias.y;
    if (l >= 3) { float2 v = *(const float2*)(xcol + (size_t)(bl - 3) * 2048);
                  a0 = fmaf(v.x, w0.x, a0); a1 = fmaf(v.y, w1.x, a1); }
    if (l >= 2) { float2 v = *(const float2*)(xcol + (size_t)(bl - 2) * 2048);
                  a0 = fmaf(v.x, w0.y, a0); a1 = fmaf(v.y, w1.y, a1); }
    if (l >= 1) { float2 v = *(const float2*)(xcol + (size_t)(bl - 1) * 2048);
                  a0 = fmaf(v.x, w0.z, a0); a1 = fmaf(v.y, w1.z, a1); }
    { float2 v = *(const float2*)(xcol + (size_t)bl * 2048);
      a0 = fmaf(v.x, w0.w, a0); a1 = fmaf(v.y, w1.w, a1); }
    float y0 = a0 / (1.f + __expf(-a0));
    float y1 = a1 / (1.f + __expf(-a1));
    size_t o = (size_t)bl * 1024 + d;
    *(float2*)(g_xc + o) = make_float2(y0, y1);
    bf16 h0 = __float2bfloat16(y0), h1 = __float2bfloat16(y1);
    __nv_bfloat162 hp = __halves2bfloat162(h0, h1);
    __nv_bfloat162 lp = __floats2bfloat162_rn(y0 - __bfloat162float(h0),
                                              y1 - __bfloat162float(h1));
    *(uint32_t*)(g_xch + o) = *(uint32_t*)&hp;
    *(uint32_t*)(g_xcl + o) = *(uint32_t*)&lp;
}

// ---------------- selective scan v4: phase-split recurrence + smem transpose ----
#define TCH 32
__global__ void __launch_bounds__(128) scan_kernel(
    const float* __restrict__ A_log,
    const float* __restrict__ D_skip,
    const float* __restrict__ dtW,
    const float* __restrict__ dtb)
{
    __shared__ float Bsh[TCH][64];
    __shared__ float Csh[TCH][64];
    __shared__ float dts[4][TCH], xcs[4][TCH], zsh[4][TCH], ysh[4][TCH];
    __shared__ float psm[4][TCH][33];
    __shared__ float wts[4][8], dtb_s[4];

    const int b    = blockIdx.y;
    const int d0   = blockIdx.x * 4;
    const int tid  = threadIdx.x;
    const int wi   = tid >> 5;
    const int lane = tid & 31;
    const int d    = d0 + wi;
    const int n0   = lane << 1;

    if (tid < 32) wts[tid >> 3][tid & 7] = dtW[(tid & 7) * 1024 + d0 + (tid >> 3)];
    if (tid < 4)  dtb_s[tid] = dtb[d0 + tid];

    const float a0 = -__expf(A_log[d * 64 + n0]);
    const float a1 = -__expf(A_log[d * 64 + n0 + 1]);
    const float Dd = D_skip[d];
    float h0 = 0.f, h1 = 0.f;

    const size_t rbase = (size_t)b * 1024;
    __syncthreads();

    for (int c = 0; c < 1024 / TCH; c++) {
        const int t0 = c * TCH;
        // ---- stage B/C tiles ----
        #pragma unroll
        for (int i = tid; i < TCH * 32; i += 128) {
            int t = i >> 5, q = i & 31;
            const float* xd = g_xdbl + (rbase + t0 + t) * XDBL_N + DTR;
            *(float2*)&Bsh[t][2 * q] = *(const float2*)(xd + 2 * q);
            *(float2*)&Csh[t][2 * q] = *(const float2*)(xd + 64 + 2 * q);
        }
        // ---- stage dt (fused delta+softplus) / xc / z : 1 item per thread ----
        {
            int t = tid >> 2, di = tid & 3;
            size_t row = rbase + t0 + t;
            const float* xd = g_xdbl + row * XDBL_N;
            float acc = dtb_s[di];
            #pragma unroll
            for (int k = 0; k < DTR; k++)
                acc = fmaf(xd[k], wts[di][k], acc);
            dts[di][t] = (acc > 20.f) ? acc : log1pf(__expf(acc));
            xcs[di][t] = g_xc[row * 1024 + d0 + di];
            zsh[di][t] = g_xz[row * 2048 + 1024 + d0 + di];
        }
        __syncthreads();

        // ---- phase A: recurrence, lane-local partial dot kept in registers ----
        float p[TCH];
        #pragma unroll
        for (int t = 0; t < TCH; t++) {
            float dt = dts[wi][t];
            float xv = xcs[wi][t];
            float2 Bv = *(const float2*)&Bsh[t][n0];
            float2 Cv = *(const float2*)&Csh[t][n0];
            float dx = dt * xv;
            h0 = fmaf(__expf(dt * a0), h0, dx * Bv.x);
            h1 = fmaf(__expf(dt * a1), h1, dx * Bv.y);
            p[t] = fmaf(h0, Cv.x, h1 * Cv.y);
        }
        // ---- phase B: smem transpose; lane L reduces timestep t0+L ----
        #pragma unroll
        for (int t = 0; t < TCH; t++) psm[wi][t][lane] = p[t];
        __syncwarp();
        {
            float s0 = 0.f, s1 = 0.f, s2 = 0.f, s3 = 0.f;
            const float* row = psm[wi][lane];
            #pragma unroll
            for (int l = 0; l < 32; l += 4) {
                s0 += row[l];
                s1 += row[l + 1];
                s2 += row[l + 2];
                s3 += row[l + 3];
            }
            float sum = (s0 + s1) + (s2 + s3);
            float zv = zsh[wi][lane];
            float sg = zv / (1.f + __expf(-zv));
            ysh[wi][lane] = (sum + xcs[wi][lane] * Dd) * sg;
        }
        __syncthreads();

        // ---- cooperative bf16-split store ----
        {
            int t = tid >> 2, di = tid & 3;
            float v = ysh[di][t];
            bf16 hv = __float2bfloat16(v);
            size_t o = (rbase + t0 + t) * 1024 + d0 + di;
            g_yh[o] = hv;
            g_yl[o] = __float2bfloat16(v - __bfloat162float(hv));
        }
        __syncthreads();
    }
}

// ---------------- launcher ----------------
extern "C" void kernel_launch(void* const* d_in, const int* in_sizes, int n_in,
                              void* d_out, int out_size)
{
    const float* q_r   = (const float*)d_in[0];
    const float* q_i   = (const float*)d_in[1];
    const float* q_j   = (const float*)d_in[2];
    const float* q_k   = (const float*)d_in[3];
    const float* inWr  = (const float*)d_in[4];
    const float* inWi  = (const float*)d_in[5];
    const float* inWj  = (const float*)d_in[6];
    const float* inWk  = (const float*)d_in[7];
    const float* convw = (const float*)d_in[8];
    const float* convb = (const float*)d_in[9];
    const float* xprojW= (const float*)d_in[10];
    const float* dtW   = (const float*)d_in[11];
    const float* dtb   = (const float*)d_in[12];
    const float* A_log = (const float*)d_in[13];
    const float* Dskip = (const float*)d_in[14];
    const float* outWr = (const float*)d_in[15];
    const float* outWi = (const float*)d_in[16];
    const float* outWj = (const float*)d_in[17];
    const float* outWk = (const float*)d_in[18];

    float *xz, *xp, *xdbl;
    bf16 *winh, *winl, *wouth, *woutl, *xpwh, *xpwl, *ah, *al, *xch, *xcl, *yh, *yl;
    cudaGetSymbolAddress((void**)&xz,    g_xz);
    cudaGetSymbolAddress((void**)&xp,    g_xp);
    cudaGetSymbolAddress((void**)&xdbl,  g_xdbl);
    cudaGetSymbolAddress((void**)&winh,  g_winh);
    cudaGetSymbolAddress((void**)&winl,  g_winl);
    cudaGetSymbolAddress((void**)&wouth, g_wouth);
    cudaGetSymbolAddress((void**)&woutl, g_woutl);
    cudaGetSymbolAddress((void**)&xpwh,  g_xpwh);
    cudaGetSymbolAddress((void**)&xpwl,  g_xpwl);
    cudaGetSymbolAddress((void**)&ah,    g_ah);
    cudaGetSymbolAddress((void**)&al,    g_al);
    cudaGetSymbolAddress((void**)&xch,   g_xch);
    cudaGetSymbolAddress((void**)&xcl,   g_xcl);
    cudaGetSymbolAddress((void**)&yh,    g_yh);
    cudaGetSymbolAddress((void**)&yl,    g_yl);

    cudaFuncSetAttribute(mma_gemm<false>,
                         cudaFuncAttributeMaxDynamicSharedMemorySize, GSMEM);
    cudaFuncSetAttribute(mma_gemm<true>,
                         cudaFuncAttributeMaxDynamicSharedMemorySize, GSMEM);

    // 1) expand weights + q-split (fused prologue)
    {
        int total = 2048 * 512 + 512 * 1024 + XN_PAD * 1024 + BL * 128;
        expand_kernel<<<(total + 255) / 256, 256>>>(
            inWr, inWi, inWj, inWk, outWr, outWi, outWj, outWk, xprojW,
            q_r, q_i, q_j, q_k);
    }
    // 2) in_proj: [2048,512] x [512,2048] -> g_xz
    mma_gemm<false><<<dim3(32, 16, 1), 256, GSMEM>>>(
        ah, al, winh, winl, xz, BL, 512, 512, 2048);
    // 3) conv + SiLU + bf16 split -> g_xc, g_xch/l
    conv_silu_kernel<<<(BL * 512 + 255) / 256, 256>>>(convw, convb);
    // 4) xproj split-K=8 -> partials            <-- profiled launch (#4)
    mma_gemm<true><<<dim3(3, 16, 8), 256, GSMEM>>>(
        xch, xcl, xpwh, xpwl, xp, BL, 1024, 128, XDBL_N);
    // 5) reduce -> g_xdbl
    reduce_kernel<<<(BL * XDBL_N / 4 + 255) / 256, 256>>>(
        (const float4*)xp, (float4*)xdbl, BL * XDBL_N / 4, 8);
    // 6) scan (fused delta + gate + bf16 split) -> g_yh/l
    scan_kernel<<<dim3(256, BB), 128>>>(A_log, Dskip, dtW, dtb);
    // 7) out_proj split-K=2 -> partials
    mma_gemm<false><<<dim3(8, 16, 2), 256, GSMEM>>>(
        yh, yl, wouth, woutl, xp, BL, 1024, 512, 512);
    // 8) reduce -> d_out
    reduce_kernel<<<(BL * 512 / 4 + 255) / 256, 256>>>(
        (const float4*)xp, (float4*)d_out, BL * 512 / 4, 2);
}